// round 14
// baseline (speedup 1.0000x reference)
#include <cuda_runtime.h>
#include <cuda_fp16.h>

#define N_NODES 100000
#define N_EDGES 3200000
#define N_GRAPHS 4096
#define IN_DIM 128
#define HID 64
#define EPS 1e-5f

#define SCAN_B 512
#define NBLK ((N_NODES + SCAN_B - 1) / SCAN_B)   // 196
#define CSR_CAP (N_EDGES + 8 * N_NODES)
#define NCLS 8                                    // atomic classing factor

// ---------------- scratch (device globals; no allocation) ----------------
__device__ __half2 d_gh [(N_NODES + 1) * 32];    // sentinel row at N_NODES (zeros)
__device__ float   d_acc[N_NODES * HID];
__device__ int     d_deg [N_NODES];              // combined in-degree
__device__ int     d_deg8[NCLS * N_NODES];       // 8-way sub-histograms
__device__ int     d_cur8[NCLS * N_NODES];       // 8-way class cursors
__device__ float   d_dinv[N_NODES + 1];
__device__ int     d_off [N_NODES];
__device__ int     d_bsum[NBLK];
__device__ int     d_csr [CSR_CAP];
__device__ float   d_stat[4 * 2 * HID];
__device__ int     d_goff[N_GRAPHS + 1];
__device__ float   d_q   [N_GRAPHS * HID];

__device__ __forceinline__ void bn_to_smem(int L, const float* g, const float* be,
                                           float cnt, float* sS, float* sT) {
    if (threadIdx.x < 64) {
        int f = threadIdx.x;
        float mean = d_stat[L * 128 + f] / cnt;
        float var  = d_stat[L * 128 + 64 + f] / cnt - mean * mean;
        var = fmaxf(var, 0.f);
        float s = g[f] * rsqrtf(var + EPS);
        sS[f] = s;
        sT[f] = be[f] - mean * s;
    }
    __syncthreads();
}

__device__ __forceinline__ unsigned f2tf32(float v) {
    unsigned u;
    asm("cvt.rna.tf32.f32 %0, %1;" : "=r"(u) : "f"(v));
    return u;
}

__device__ __forceinline__ void mma_tf32(float c[4], unsigned a0, unsigned a1,
                                         unsigned a2, unsigned a3,
                                         unsigned b0, unsigned b1) {
    asm volatile(
        "mma.sync.aligned.m16n8k8.row.col.f32.tf32.tf32.f32 "
        "{%0,%1,%2,%3}, {%4,%5,%6,%7}, {%8,%9}, {%0,%1,%2,%3};"
        : "+f"(c[0]), "+f"(c[1]), "+f"(c[2]), "+f"(c[3])
        : "r"(a0), "r"(a1), "r"(a2), "r"(a3), "r"(b0), "r"(b1));
}

// ---------------- setup kernels ----------------
__global__ void k_zero() {
    int i = blockIdx.x * blockDim.x + threadIdx.x;
    if (i < 4 * 2 * HID) d_stat[i] = 0.f;
}

__global__ void k_goff(const int* __restrict__ batch) {
    int g = blockIdx.x * blockDim.x + threadIdx.x;
    if (g > N_GRAPHS) return;
    int lo = 0, hi = N_NODES;
    while (lo < hi) {
        int mid = (lo + hi) >> 1;
        if (batch[mid] < g) lo = mid + 1; else hi = mid;
    }
    d_goff[g] = lo;
}

// 8-way sub-histogram degree count
__global__ void k_deg(const int* __restrict__ col) {
    int idx = blockIdx.x * blockDim.x + threadIdx.x;
    int stride = gridDim.x * blockDim.x;
    int* hist = d_deg8 + (blockIdx.x & (NCLS - 1)) * N_NODES;
    for (int e = idx; e < N_EDGES; e += stride)
        atomicAdd(&hist[col[e]], 1);
}

// scan of PADDED in-degree (sums 8 histograms, writes combined deg)
__global__ void k_scanA() {
    __shared__ int s[SCAN_B];
    int i = blockIdx.x * SCAN_B + threadIdx.x;
    int v = 0;
    if (i < N_NODES) {
        int e = 0;
#pragma unroll
        for (int c = 0; c < NCLS; c++) e += d_deg8[c * N_NODES + i];
        d_deg[i] = e;
        v = (e + 7) & ~7;
    }
    s[threadIdx.x] = v;
    __syncthreads();
    for (int off = 1; off < SCAN_B; off <<= 1) {
        int t = (threadIdx.x >= off) ? s[threadIdx.x - off] : 0;
        __syncthreads();
        s[threadIdx.x] += t;
        __syncthreads();
    }
    if (i < N_NODES) d_off[i] = s[threadIdx.x] - v;
    if (threadIdx.x == SCAN_B - 1) d_bsum[blockIdx.x] = s[SCAN_B - 1];
}

// fused scanB + scanC + dinv + sentinel-pad + 8-way class cursor prefixes
__global__ void k_scanC2() {
    __shared__ int sred[256];
    int sb = blockIdx.x >> 1;
    int v = (threadIdx.x < sb) ? d_bsum[threadIdx.x] : 0;
    sred[threadIdx.x] = v;
    __syncthreads();
#pragma unroll
    for (int off = 128; off > 0; off >>= 1) {
        if (threadIdx.x < off) sred[threadIdx.x] += sred[threadIdx.x + off];
        __syncthreads();
    }
    int pref = sred[0];
    int i = blockIdx.x * 256 + threadIdx.x;
    if (i < N_NODES) {
        int o = d_off[i] + pref;
        int e = d_deg[i];
        d_off[i] = o;
        d_dinv[i] = rsqrtf((float)(e + 1));      // +1 self loop
        // per-class cursor start = o + prefix of class counts
        int run = o;
#pragma unroll
        for (int c = 0; c < NCLS; c++) {
            d_cur8[c * N_NODES + i] = run;
            run += d_deg8[c * N_NODES + i];
        }
        int padlen = (e + 7) & ~7;
        for (int k = e; k < padlen; k++) d_csr[o + k] = N_NODES;
    }
    if (blockIdx.x == 0 && threadIdx.x == 0) d_dinv[N_NODES] = 0.f;
}

// classed fill: each block bumps only its own class cursor (8x less contention)
__global__ void k_fill(const int* __restrict__ row, const int* __restrict__ col) {
    int idx = blockIdx.x * blockDim.x + threadIdx.x;
    int stride = gridDim.x * blockDim.x;
    int* cur = d_cur8 + (blockIdx.x & (NCLS - 1)) * N_NODES;
    for (int e = idx; e < N_EDGES; e += stride) {
        int pos = atomicAdd(&cur[col[e]], 1);
        d_csr[pos] = row[e];
    }
}

// ---------------- GEMM0 (layer 0, FFMA, side stream) ----------------
__global__ void k_gemm0(const float* __restrict__ in, const float* __restrict__ W) {
    __shared__ float sW[64 * 64];
    __shared__ float sX[64 * 68];
    const int tr = threadIdx.x & 15;
    const int tc = threadIdx.x >> 4;
    const int base = blockIdx.x * 64;

    float acc[4][4];
#pragma unroll
    for (int i = 0; i < 4; i++)
#pragma unroll
        for (int j = 0; j < 4; j++) acc[i][j] = 0.f;

    for (int kt = 0; kt < 2; kt++) {
        for (int i = threadIdx.x; i < 4096; i += 256)
            sW[i] = W[kt * 4096 + i];
        for (int i = threadIdx.x; i < 4096; i += 256) {
            int n = i >> 6, k = i & 63;
            int ng = base + n;
            sX[k * 68 + n] = (ng < N_NODES) ? in[ng * 128 + kt * 64 + k] : 0.f;
        }
        __syncthreads();
#pragma unroll 8
        for (int kk = 0; kk < 64; kk++) {
            float4 xv = *reinterpret_cast<float4*>(&sX[kk * 68 + tr * 4]);
            float4 wv = *reinterpret_cast<float4*>(&sW[kk * 64 + tc * 4]);
            acc[0][0] = fmaf(xv.x, wv.x, acc[0][0]);
            acc[0][1] = fmaf(xv.x, wv.y, acc[0][1]);
            acc[0][2] = fmaf(xv.x, wv.z, acc[0][2]);
            acc[0][3] = fmaf(xv.x, wv.w, acc[0][3]);
            acc[1][0] = fmaf(xv.y, wv.x, acc[1][0]);
            acc[1][1] = fmaf(xv.y, wv.y, acc[1][1]);
            acc[1][2] = fmaf(xv.y, wv.z, acc[1][2]);
            acc[1][3] = fmaf(xv.y, wv.w, acc[1][3]);
            acc[2][0] = fmaf(xv.z, wv.x, acc[2][0]);
            acc[2][1] = fmaf(xv.z, wv.y, acc[2][1]);
            acc[2][2] = fmaf(xv.z, wv.z, acc[2][2]);
            acc[2][3] = fmaf(xv.z, wv.w, acc[2][3]);
            acc[3][0] = fmaf(xv.w, wv.x, acc[3][0]);
            acc[3][1] = fmaf(xv.w, wv.y, acc[3][1]);
            acc[3][2] = fmaf(xv.w, wv.z, acc[3][2]);
            acc[3][3] = fmaf(xv.w, wv.w, acc[3][3]);
        }
        __syncthreads();
    }
#pragma unroll
    for (int i = 0; i < 4; i++) {
        int n = base + tr * 4 + i;
        if (n < N_NODES) {
            __half2 h0 = __floats2half2_rn(acc[i][0], acc[i][1]);
            __half2 h1 = __floats2half2_rn(acc[i][2], acc[i][3]);
            uint2 u;
            u.x = *reinterpret_cast<unsigned*>(&h0);
            u.y = *reinterpret_cast<unsigned*>(&h1);
            *reinterpret_cast<uint2*>(&d_gh[n * 32 + tc * 2]) = u;
        }
    }
}

// ---------------- tf32 MMA GEMM (layers 1,2) ----------------
__global__ void k_gemm_tf32(const float* __restrict__ W, int stL,
                            const float* __restrict__ g, const float* __restrict__ be) {
    __shared__ unsigned sA[64 * 68];
    __shared__ unsigned sB[64 * 68];
    __shared__ float sS[64], sT[64];
    const int base = blockIdx.x * 64;

    bn_to_smem(stL, g, be, (float)N_NODES, sS, sT);

    for (int i = threadIdx.x; i < 4096; i += 256) {
        int k = i >> 6, f = i & 63;
        sB[k * 68 + f] = f2tf32(W[i]);
    }
    for (int i = threadIdx.x; i < 4096; i += 256) {
        int m = i >> 6, k = i & 63;
        int ng = base + m;
        float v = 0.f;
        if (ng < N_NODES)
            v = fmaxf(fmaf(d_acc[ng * 64 + k], sS[k], sT[k]), 0.f);
        sA[m * 68 + k] = f2tf32(v);
    }
    __syncthreads();

    const int wid = threadIdx.x >> 5;
    const int lane = threadIdx.x & 31;
    const int gid = lane >> 2;
    const int tig = lane & 3;
    const int wm = (wid & 3) * 16;
    const int wn = (wid >> 2) * 32;

    float c[4][4];
#pragma unroll
    for (int nn = 0; nn < 4; nn++)
#pragma unroll
        for (int i = 0; i < 4; i++) c[nn][i] = 0.f;

#pragma unroll
    for (int k0 = 0; k0 < 64; k0 += 8) {
        unsigned a0 = sA[(wm + gid) * 68 + k0 + tig];
        unsigned a1 = sA[(wm + gid + 8) * 68 + k0 + tig];
        unsigned a2 = sA[(wm + gid) * 68 + k0 + tig + 4];
        unsigned a3 = sA[(wm + gid + 8) * 68 + k0 + tig + 4];
#pragma unroll
        for (int nn = 0; nn < 4; nn++) {
            unsigned b0 = sB[(k0 + tig) * 68 + wn + nn * 8 + gid];
            unsigned b1 = sB[(k0 + tig + 4) * 68 + wn + nn * 8 + gid];
            mma_tf32(c[nn], a0, a1, a2, a3, b0, b1);
        }
    }

    int n0 = base + wm + gid;
    int n1 = n0 + 8;
    float dv0 = (n0 < N_NODES) ? d_dinv[n0] : 0.f;
    float dv1 = (n1 < N_NODES) ? d_dinv[n1] : 0.f;
#pragma unroll
    for (int nn = 0; nn < 4; nn++) {
        int f = wn + nn * 8 + 2 * tig;
        if (n0 < N_NODES)
            d_gh[n0 * 32 + (f >> 1)] = __floats2half2_rn(c[nn][0] * dv0, c[nn][1] * dv0);
        if (n1 < N_NODES)
            d_gh[n1 * 32 + (f >> 1)] = __floats2half2_rn(c[nn][2] * dv1, c[nn][3] * dv1);
    }
}

// ---------------- branchless padded-CSR gather-aggregate (R10-proven) -------
template <bool ROWDINV>
__global__ void k_aggr4(int L) {
    __shared__ float ssum[16 * 65];
    __shared__ float ssq [16 * 65];
    const int w = threadIdx.x >> 5;
    const int lane = threadIdx.x & 31;
    const int grp = lane >> 3;
    const int sub = lane & 7;
    const int node = blockIdx.x * 16 + w;
    const uint4* __restrict__ gh4 = reinterpret_cast<const uint4*>(d_gh);

    float acc[8];
#pragma unroll
    for (int i = 0; i < 8; i++) acc[i] = 0.f;

    if (node < N_NODES) {
        const int start = d_off[node];
        const int e = d_deg[node];
        const int padlen = (e + 7) & ~7;

        for (int j = 0; j < padlen; j += 8) {
            int r0 = __ldg(&d_csr[start + j + grp]);
            int r1 = __ldg(&d_csr[start + j + 4 + grp]);
            uint4 u0 = __ldg(&gh4[r0 * 8 + sub]);
            uint4 u1 = __ldg(&gh4[r1 * 8 + sub]);
            float dm0 = 1.f, dm1 = 1.f;
            if (ROWDINV) { dm0 = __ldg(&d_dinv[r0]); dm1 = __ldg(&d_dinv[r1]); }
            float2 f;
            f = __half22float2(*reinterpret_cast<__half2*>(&u0.x));
            acc[0] = fmaf(dm0, f.x, acc[0]); acc[1] = fmaf(dm0, f.y, acc[1]);
            f = __half22float2(*reinterpret_cast<__half2*>(&u0.y));
            acc[2] = fmaf(dm0, f.x, acc[2]); acc[3] = fmaf(dm0, f.y, acc[3]);
            f = __half22float2(*reinterpret_cast<__half2*>(&u0.z));
            acc[4] = fmaf(dm0, f.x, acc[4]); acc[5] = fmaf(dm0, f.y, acc[5]);
            f = __half22float2(*reinterpret_cast<__half2*>(&u0.w));
            acc[6] = fmaf(dm0, f.x, acc[6]); acc[7] = fmaf(dm0, f.y, acc[7]);
            f = __half22float2(*reinterpret_cast<__half2*>(&u1.x));
            acc[0] = fmaf(dm1, f.x, acc[0]); acc[1] = fmaf(dm1, f.y, acc[1]);
            f = __half22float2(*reinterpret_cast<__half2*>(&u1.y));
            acc[2] = fmaf(dm1, f.x, acc[2]); acc[3] = fmaf(dm1, f.y, acc[3]);
            f = __half22float2(*reinterpret_cast<__half2*>(&u1.z));
            acc[4] = fmaf(dm1, f.x, acc[4]); acc[5] = fmaf(dm1, f.y, acc[5]);
            f = __half22float2(*reinterpret_cast<__half2*>(&u1.w));
            acc[6] = fmaf(dm1, f.x, acc[6]); acc[7] = fmaf(dm1, f.y, acc[7]);
        }

        if (grp == 0) {   // self loop
            float selfs = ROWDINV ? d_dinv[node] : 1.f;
            uint4 su = gh4[node * 8 + sub];
            float2 f;
            f = __half22float2(*reinterpret_cast<__half2*>(&su.x));
            acc[0] = fmaf(selfs, f.x, acc[0]); acc[1] = fmaf(selfs, f.y, acc[1]);
            f = __half22float2(*reinterpret_cast<__half2*>(&su.y));
            acc[2] = fmaf(selfs, f.x, acc[2]); acc[3] = fmaf(selfs, f.y, acc[3]);
            f = __half22float2(*reinterpret_cast<__half2*>(&su.z));
            acc[4] = fmaf(selfs, f.x, acc[4]); acc[5] = fmaf(selfs, f.y, acc[5]);
            f = __half22float2(*reinterpret_cast<__half2*>(&su.w));
            acc[6] = fmaf(selfs, f.x, acc[6]); acc[7] = fmaf(selfs, f.y, acc[7]);
        }
    }

#pragma unroll
    for (int i = 0; i < 8; i++) acc[i] += __shfl_xor_sync(0xffffffffu, acc[i], 8);
#pragma unroll
    for (int i = 0; i < 8; i++) acc[i] += __shfl_xor_sync(0xffffffffu, acc[i], 16);

    float dv = (node < N_NODES) ? d_dinv[node] : 0.f;
#pragma unroll
    for (int i = 0; i < 8; i++) acc[i] *= dv;

    if (grp == 0) {
        if (node < N_NODES) {
            float4 o0 = make_float4(acc[0], acc[1], acc[2], acc[3]);
            float4 o1 = make_float4(acc[4], acc[5], acc[6], acc[7]);
            *reinterpret_cast<float4*>(&d_acc[node * 64 + sub * 8])     = o0;
            *reinterpret_cast<float4*>(&d_acc[node * 64 + sub * 8 + 4]) = o1;
        }
#pragma unroll
        for (int i = 0; i < 8; i++) {
            ssum[w * 65 + sub * 8 + i] = (node < N_NODES) ? acc[i] : 0.f;
            ssq [w * 65 + sub * 8 + i] = (node < N_NODES) ? acc[i] * acc[i] : 0.f;
        }
    }
    __syncthreads();
    if (threadIdx.x < 128) {
        int feat = threadIdx.x & 63;
        bool isq = threadIdx.x >= 64;
        const float* src = isq ? ssq : ssum;
        float a = 0.f;
#pragma unroll
        for (int ww = 0; ww < 16; ww++) a += src[ww * 65 + feat];
        atomicAdd(&d_stat[L * 128 + (isq ? 64 : 0) + feat], a);
    }
}

// ---------------- fused pool + fc1 ----------------
__global__ void k_poolfc1(const float* __restrict__ g, const float* __restrict__ be,
                          const float* __restrict__ W1) {
    __shared__ float sS[64], sT[64];
    __shared__ float sp[8 * 64];
    __shared__ float sq1[8 * 65], sq2[8 * 65];
    bn_to_smem(2, g, be, (float)N_NODES, sS, sT);

    const int w = threadIdx.x >> 5;
    const int lane = threadIdx.x & 31;
    const int gbase = blockIdx.x * 8;
    const int gidx = gbase + w;
    {
        const int s = d_goff[gidx];
        const int e = d_goff[gidx + 1];
        const int half = lane >> 4;
        const int chunk = lane & 15;
        float4 a = make_float4(0.f, 0.f, 0.f, 0.f);
        for (int n = s + half; n < e; n += 2) {
            float4 v = *reinterpret_cast<const float4*>(&d_acc[n * 64 + chunk * 4]);
            a.x += fmaxf(fmaf(v.x, sS[chunk * 4 + 0], sT[chunk * 4 + 0]), 0.f);
            a.y += fmaxf(fmaf(v.y, sS[chunk * 4 + 1], sT[chunk * 4 + 1]), 0.f);
            a.z += fmaxf(fmaf(v.z, sS[chunk * 4 + 2], sT[chunk * 4 + 2]), 0.f);
            a.w += fmaxf(fmaf(v.w, sS[chunk * 4 + 3], sT[chunk * 4 + 3]), 0.f);
        }
        a.x += __shfl_xor_sync(0xffffffffu, a.x, 16);
        a.y += __shfl_xor_sync(0xffffffffu, a.y, 16);
        a.z += __shfl_xor_sync(0xffffffffu, a.z, 16);
        a.w += __shfl_xor_sync(0xffffffffu, a.w, 16);
        if (half == 0) {
            float inv = 1.0f / fmaxf((float)(e - s), 1.0f);
            float4 o = make_float4(a.x * inv, a.y * inv, a.z * inv, a.w * inv);
            *reinterpret_cast<float4*>(&sp[w * 64 + chunk * 4]) = o;
        }
    }
    __syncthreads();

    const int f = threadIdx.x & 63;
    const int g0 = threadIdx.x >> 6;
#pragma unroll
    for (int pass = 0; pass < 2; pass++) {
        int gg = g0 + pass * 4;
        float q = 0.f;
        const float* pv = &sp[gg * 64];
#pragma unroll 8
        for (int k = 0; k < 64; k++)
            q = fmaf(pv[k], __ldg(&W1[k * 64 + f]), q);
        d_q[(gbase + gg) * 64 + f] = q;
        sq1[gg * 65 + f] = q;
        sq2[gg * 65 + f] = q * q;
    }
    __syncthreads();
    if (threadIdx.x < 128) {
        int feat = threadIdx.x & 63;
        bool isq = threadIdx.x >= 64;
        const float* src = isq ? sq2 : sq1;
        float a = 0.f;
#pragma unroll
        for (int gg = 0; gg < 8; gg++) a += src[gg * 65 + feat];
        atomicAdd(&d_stat[3 * 128 + (isq ? 64 : 0) + feat], a);
    }
}

__global__ void k_fc2(const float* __restrict__ W2, const float* __restrict__ b2,
                      const float* __restrict__ gf, const float* __restrict__ bf,
                      float* __restrict__ out) {
    __shared__ float sS[64], sT[64];
    bn_to_smem(3, gf, bf, (float)N_GRAPHS, sS, sT);
    int g = blockIdx.x * (blockDim.x / 32) + (threadIdx.x >> 5);
    int lane = threadIdx.x & 31;
    if (g >= N_GRAPHS) return;
    float acc = 0.f;
#pragma unroll
    for (int j = 0; j < 2; j++) {
        int f = lane + 32 * j;
        float z = fmaxf(fmaf(d_q[g * 64 + f], sS[f], sT[f]), 0.f);
        acc = fmaf(z, W2[f], acc);
    }
#pragma unroll
    for (int o = 16; o > 0; o >>= 1)
        acc += __shfl_down_sync(0xffffffffu, acc, o);
    if (lane == 0) out[g] = acc + b2[0];
}

// ---------------- launch ----------------
extern "C" void kernel_launch(void* const* d_in, const int* in_sizes, int n_in,
                              void* d_out, int out_size) {
    const float* x     = (const float*)d_in[0];
    const int*   ei    = (const int*)d_in[1];
    const int*   row   = ei;
    const int*   col   = ei + N_EDGES;
    const int*   batch = (const int*)d_in[2];
    const float* Wc0 = (const float*)d_in[3];
    const float* g0  = (const float*)d_in[5];
    const float* be0 = (const float*)d_in[6];
    const float* Wc1 = (const float*)d_in[7];
    const float* g1  = (const float*)d_in[9];
    const float* be1 = (const float*)d_in[10];
    const float* Wc2 = (const float*)d_in[11];
    const float* g2  = (const float*)d_in[13];
    const float* be2 = (const float*)d_in[14];
    const float* W1  = (const float*)d_in[15];
    const float* gf  = (const float*)d_in[17];
    const float* bf  = (const float*)d_in[18];
    const float* W2  = (const float*)d_in[19];
    const float* b2  = (const float*)d_in[20];
    float* out = (float*)d_out;

    static cudaStream_t s1 = nullptr;
    static cudaEvent_t eFork = nullptr, eGemm0 = nullptr;
    static void* deg8Addr = nullptr;
    if (s1 == nullptr) {
        cudaStreamCreateWithFlags(&s1, cudaStreamNonBlocking);
        cudaEventCreateWithFlags(&eFork, cudaEventDisableTiming);
        cudaEventCreateWithFlags(&eGemm0, cudaEventDisableTiming);
        cudaGetSymbolAddress(&deg8Addr, d_deg8);
    }

    const int GEMM_GRID = (N_NODES + 63) / 64;              // 1563
    const int AGGR_GRID = (N_NODES + 15) / 16;              // 6250
    const int N256 = (N_NODES + 255) / 256;                 // 391

    // Side stream: zero stats, graph offsets, GEMM0 (graph-structure-free)
    cudaEventRecord(eFork, 0);
    cudaStreamWaitEvent(s1, eFork, 0);
    k_zero<<<2, 256, 0, s1>>>();
    k_goff<<<(N_GRAPHS + 256) / 256, 256, 0, s1>>>(batch);
    k_gemm0<<<GEMM_GRID, 256, 0, s1>>>(x, Wc0);
    cudaEventRecord(eGemm0, s1);

    // Critical path: packed padded CSR build, 8-way classed atomics
    cudaMemsetAsync(deg8Addr, 0, NCLS * N_NODES * sizeof(int), 0);
    k_deg <<<8192, 256>>>(col);
    k_scanA<<<NBLK, SCAN_B>>>();
    k_scanC2<<<N256, 256>>>();
    k_fill<<<8192, 256>>>(row, col);

    cudaStreamWaitEvent(0, eGemm0, 0);

    // layer 0
    k_aggr4<true><<<AGGR_GRID, 512>>>(0);
    // layer 1 (tf32 MMA GEMM)
    k_gemm_tf32<<<GEMM_GRID, 256>>>(Wc1, 0, g0, be0);
    k_aggr4<false><<<AGGR_GRID, 512>>>(1);
    // layer 2
    k_gemm_tf32<<<GEMM_GRID, 256>>>(Wc2, 1, g1, be1);
    k_aggr4<false><<<AGGR_GRID, 512>>>(2);

    // pooling + head (pool/fc1 fused)
    k_poolfc1<<<N_GRAPHS / 8, 256>>>(g2, be2, W1);
    k_fc2<<<N_GRAPHS / 8, 256>>>(W2, b2, gf, bf, out);
}

// round 15
// speedup vs baseline: 1.0264x; 1.0264x over previous
#include <cuda_runtime.h>
#include <cuda_fp16.h>

#define N_NODES 100000
#define N_EDGES 3200000
#define N_GRAPHS 4096
#define IN_DIM 128
#define HID 64
#define EPS 1e-5f

#define SCAN_B 512
#define NBLK ((N_NODES + SCAN_B - 1) / SCAN_B)   // 196
#define CSR_CAP (N_EDGES + 8 * N_NODES)

// ---------------- scratch (device globals; no allocation) ----------------
__device__ __half2 d_gh [(N_NODES + 1) * 32];    // sentinel row at N_NODES (zeros)
__device__ float   d_acc[N_NODES * HID];
__device__ int     d_deg [N_NODES];              // combined in-degree (written by scanA)
__device__ int     d_deg4[4 * N_NODES];          // 4-way sub-histograms
__device__ float   d_dinv[N_NODES + 1];
__device__ int     d_off [N_NODES];
__device__ int     d_cur [N_NODES];
__device__ int     d_bsum[NBLK];
__device__ int     d_csr [CSR_CAP];
__device__ float   d_stat[4 * 2 * HID];
__device__ int     d_goff[N_GRAPHS + 1];
__device__ float   d_q   [N_GRAPHS * HID];

__device__ __forceinline__ void bn_to_smem(int L, const float* g, const float* be,
                                           float cnt, float* sS, float* sT) {
    if (threadIdx.x < 64) {
        int f = threadIdx.x;
        float mean = d_stat[L * 128 + f] / cnt;
        float var  = d_stat[L * 128 + 64 + f] / cnt - mean * mean;
        var = fmaxf(var, 0.f);
        float s = g[f] * rsqrtf(var + EPS);
        sS[f] = s;
        sT[f] = be[f] - mean * s;
    }
    __syncthreads();
}

__device__ __forceinline__ unsigned f2tf32(float v) {
    unsigned u;
    asm("cvt.rna.tf32.f32 %0, %1;" : "=r"(u) : "f"(v));
    return u;
}

__device__ __forceinline__ void mma_tf32(float c[4], unsigned a0, unsigned a1,
                                         unsigned a2, unsigned a3,
                                         unsigned b0, unsigned b1) {
    asm volatile(
        "mma.sync.aligned.m16n8k8.row.col.f32.tf32.tf32.f32 "
        "{%0,%1,%2,%3}, {%4,%5,%6,%7}, {%8,%9}, {%0,%1,%2,%3};"
        : "+f"(c[0]), "+f"(c[1]), "+f"(c[2]), "+f"(c[3])
        : "r"(a0), "r"(a1), "r"(a2), "r"(a3), "r"(b0), "r"(b1));
}

// L2-only (L1-bypass) 128-bit load for random gathers
__device__ __forceinline__ uint4 ldcg_v4(const uint4* p) {
    uint4 v;
    asm volatile("ld.global.cg.v4.u32 {%0,%1,%2,%3}, [%4];"
                 : "=r"(v.x), "=r"(v.y), "=r"(v.z), "=r"(v.w) : "l"(p));
    return v;
}

// ---------------- setup kernels ----------------
__global__ void k_zero() {
    int i = blockIdx.x * blockDim.x + threadIdx.x;
    if (i < 4 * 2 * HID) d_stat[i] = 0.f;
}

__global__ void k_goff(const int* __restrict__ batch) {
    int g = blockIdx.x * blockDim.x + threadIdx.x;
    if (g > N_GRAPHS) return;
    int lo = 0, hi = N_NODES;
    while (lo < hi) {
        int mid = (lo + hi) >> 1;
        if (batch[mid] < g) lo = mid + 1; else hi = mid;
    }
    d_goff[g] = lo;
}

// 4-way sub-histogram degree count (R13-proven)
__global__ void k_deg(const int* __restrict__ col) {
    int idx = blockIdx.x * blockDim.x + threadIdx.x;
    int stride = gridDim.x * blockDim.x;
    int* hist = d_deg4 + (blockIdx.x & 3) * N_NODES;
    for (int e = idx; e < N_EDGES; e += stride)
        atomicAdd(&hist[col[e]], 1);
}

// scan of PADDED in-degree (sums 4 histograms, writes combined deg back)
__global__ void k_scanA() {
    __shared__ int s[SCAN_B];
    int i = blockIdx.x * SCAN_B + threadIdx.x;
    int v = 0;
    if (i < N_NODES) {
        int e = d_deg4[i] + d_deg4[N_NODES + i]
              + d_deg4[2 * N_NODES + i] + d_deg4[3 * N_NODES + i];
        d_deg[i] = e;
        v = (e + 7) & ~7;
    }
    s[threadIdx.x] = v;
    __syncthreads();
    for (int off = 1; off < SCAN_B; off <<= 1) {
        int t = (threadIdx.x >= off) ? s[threadIdx.x - off] : 0;
        __syncthreads();
        s[threadIdx.x] += t;
        __syncthreads();
    }
    if (i < N_NODES) d_off[i] = s[threadIdx.x] - v;
    if (threadIdx.x == SCAN_B - 1) d_bsum[blockIdx.x] = s[SCAN_B - 1];
}

// fused scanB + scanC + dinv + sentinel-pad writes
__global__ void k_scanC2() {
    __shared__ int sred[256];
    int sb = blockIdx.x >> 1;
    int v = (threadIdx.x < sb) ? d_bsum[threadIdx.x] : 0;
    sred[threadIdx.x] = v;
    __syncthreads();
#pragma unroll
    for (int off = 128; off > 0; off >>= 1) {
        if (threadIdx.x < off) sred[threadIdx.x] += sred[threadIdx.x + off];
        __syncthreads();
    }
    int pref = sred[0];
    int i = blockIdx.x * 256 + threadIdx.x;
    if (i < N_NODES) {
        int o = d_off[i] + pref;
        int e = d_deg[i];
        d_off[i] = o;
        d_cur[i] = o;
        d_dinv[i] = rsqrtf((float)(e + 1));      // +1 self loop
        int padlen = (e + 7) & ~7;
        for (int k = e; k < padlen; k++) d_csr[o + k] = N_NODES;
    }
    if (blockIdx.x == 0 && threadIdx.x == 0) d_dinv[N_NODES] = 0.f;
}

__global__ void k_fill(const int* __restrict__ row, const int* __restrict__ col) {
    int idx = blockIdx.x * blockDim.x + threadIdx.x;
    int stride = gridDim.x * blockDim.x;
    for (int e = idx; e < N_EDGES; e += stride) {
        int pos = atomicAdd(&d_cur[col[e]], 1);
        d_csr[pos] = row[e];
    }
}

// ---------------- GEMM0 (layer 0, FFMA, side stream) ----------------
__global__ void k_gemm0(const float* __restrict__ in, const float* __restrict__ W) {
    __shared__ float sW[64 * 64];
    __shared__ float sX[64 * 68];
    const int tr = threadIdx.x & 15;
    const int tc = threadIdx.x >> 4;
    const int base = blockIdx.x * 64;

    float acc[4][4];
#pragma unroll
    for (int i = 0; i < 4; i++)
#pragma unroll
        for (int j = 0; j < 4; j++) acc[i][j] = 0.f;

    for (int kt = 0; kt < 2; kt++) {
        for (int i = threadIdx.x; i < 4096; i += 256)
            sW[i] = W[kt * 4096 + i];
        for (int i = threadIdx.x; i < 4096; i += 256) {
            int n = i >> 6, k = i & 63;
            int ng = base + n;
            sX[k * 68 + n] = (ng < N_NODES) ? in[ng * 128 + kt * 64 + k] : 0.f;
        }
        __syncthreads();
#pragma unroll 8
        for (int kk = 0; kk < 64; kk++) {
            float4 xv = *reinterpret_cast<float4*>(&sX[kk * 68 + tr * 4]);
            float4 wv = *reinterpret_cast<float4*>(&sW[kk * 64 + tc * 4]);
            acc[0][0] = fmaf(xv.x, wv.x, acc[0][0]);
            acc[0][1] = fmaf(xv.x, wv.y, acc[0][1]);
            acc[0][2] = fmaf(xv.x, wv.z, acc[0][2]);
            acc[0][3] = fmaf(xv.x, wv.w, acc[0][3]);
            acc[1][0] = fmaf(xv.y, wv.x, acc[1][0]);
            acc[1][1] = fmaf(xv.y, wv.y, acc[1][1]);
            acc[1][2] = fmaf(xv.y, wv.z, acc[1][2]);
            acc[1][3] = fmaf(xv.y, wv.w, acc[1][3]);
            acc[2][0] = fmaf(xv.z, wv.x, acc[2][0]);
            acc[2][1] = fmaf(xv.z, wv.y, acc[2][1]);
            acc[2][2] = fmaf(xv.z, wv.z, acc[2][2]);
            acc[2][3] = fmaf(xv.z, wv.w, acc[2][3]);
            acc[3][0] = fmaf(xv.w, wv.x, acc[3][0]);
            acc[3][1] = fmaf(xv.w, wv.y, acc[3][1]);
            acc[3][2] = fmaf(xv.w, wv.z, acc[3][2]);
            acc[3][3] = fmaf(xv.w, wv.w, acc[3][3]);
        }
        __syncthreads();
    }
#pragma unroll
    for (int i = 0; i < 4; i++) {
        int n = base + tr * 4 + i;
        if (n < N_NODES) {
            __half2 h0 = __floats2half2_rn(acc[i][0], acc[i][1]);
            __half2 h1 = __floats2half2_rn(acc[i][2], acc[i][3]);
            uint2 u;
            u.x = *reinterpret_cast<unsigned*>(&h0);
            u.y = *reinterpret_cast<unsigned*>(&h1);
            *reinterpret_cast<uint2*>(&d_gh[n * 32 + tc * 2]) = u;
        }
    }
}

// ---------------- tf32 MMA GEMM (layers 1,2) ----------------
__global__ void k_gemm_tf32(const float* __restrict__ W, int stL,
                            const float* __restrict__ g, const float* __restrict__ be) {
    __shared__ unsigned sA[64 * 68];
    __shared__ unsigned sB[64 * 68];
    __shared__ float sS[64], sT[64];
    const int base = blockIdx.x * 64;

    bn_to_smem(stL, g, be, (float)N_NODES, sS, sT);

    for (int i = threadIdx.x; i < 4096; i += 256) {
        int k = i >> 6, f = i & 63;
        sB[k * 68 + f] = f2tf32(W[i]);
    }
    for (int i = threadIdx.x; i < 4096; i += 256) {
        int m = i >> 6, k = i & 63;
        int ng = base + m;
        float v = 0.f;
        if (ng < N_NODES)
            v = fmaxf(fmaf(d_acc[ng * 64 + k], sS[k], sT[k]), 0.f);
        sA[m * 68 + k] = f2tf32(v);
    }
    __syncthreads();

    const int wid = threadIdx.x >> 5;
    const int lane = threadIdx.x & 31;
    const int gid = lane >> 2;
    const int tig = lane & 3;
    const int wm = (wid & 3) * 16;
    const int wn = (wid >> 2) * 32;

    float c[4][4];
#pragma unroll
    for (int nn = 0; nn < 4; nn++)
#pragma unroll
        for (int i = 0; i < 4; i++) c[nn][i] = 0.f;

#pragma unroll
    for (int k0 = 0; k0 < 64; k0 += 8) {
        unsigned a0 = sA[(wm + gid) * 68 + k0 + tig];
        unsigned a1 = sA[(wm + gid + 8) * 68 + k0 + tig];
        unsigned a2 = sA[(wm + gid) * 68 + k0 + tig + 4];
        unsigned a3 = sA[(wm + gid + 8) * 68 + k0 + tig + 4];
#pragma unroll
        for (int nn = 0; nn < 4; nn++) {
            unsigned b0 = sB[(k0 + tig) * 68 + wn + nn * 8 + gid];
            unsigned b1 = sB[(k0 + tig + 4) * 68 + wn + nn * 8 + gid];
            mma_tf32(c[nn], a0, a1, a2, a3, b0, b1);
        }
    }

    int n0 = base + wm + gid;
    int n1 = n0 + 8;
    float dv0 = (n0 < N_NODES) ? d_dinv[n0] : 0.f;
    float dv1 = (n1 < N_NODES) ? d_dinv[n1] : 0.f;
#pragma unroll
    for (int nn = 0; nn < 4; nn++) {
        int f = wn + nn * 8 + 2 * tig;
        if (n0 < N_NODES)
            d_gh[n0 * 32 + (f >> 1)] = __floats2half2_rn(c[nn][0] * dv0, c[nn][1] * dv0);
        if (n1 < N_NODES)
            d_gh[n1 * 32 + (f >> 1)] = __floats2half2_rn(c[nn][2] * dv1, c[nn][3] * dv1);
    }
}

// ---------------- branchless padded-CSR gather-aggregate --------------------
// Identical to R13 winner except gh gathers use .cg (L2-only, no L1 thrash).
template <bool ROWDINV>
__global__ void k_aggr4(int L) {
    __shared__ float ssum[16 * 65];
    __shared__ float ssq [16 * 65];
    const int w = threadIdx.x >> 5;
    const int lane = threadIdx.x & 31;
    const int grp = lane >> 3;
    const int sub = lane & 7;
    const int node = blockIdx.x * 16 + w;
    const uint4* __restrict__ gh4 = reinterpret_cast<const uint4*>(d_gh);

    float acc[8];
#pragma unroll
    for (int i = 0; i < 8; i++) acc[i] = 0.f;

    if (node < N_NODES) {
        const int start = d_off[node];
        const int e = d_deg[node];
        const int padlen = (e + 7) & ~7;

        for (int j = 0; j < padlen; j += 8) {
            int r0 = __ldg(&d_csr[start + j + grp]);
            int r1 = __ldg(&d_csr[start + j + 4 + grp]);
            uint4 u0 = ldcg_v4(&gh4[r0 * 8 + sub]);
            uint4 u1 = ldcg_v4(&gh4[r1 * 8 + sub]);
            float dm0 = 1.f, dm1 = 1.f;
            if (ROWDINV) { dm0 = __ldg(&d_dinv[r0]); dm1 = __ldg(&d_dinv[r1]); }
            float2 f;
            f = __half22float2(*reinterpret_cast<__half2*>(&u0.x));
            acc[0] = fmaf(dm0, f.x, acc[0]); acc[1] = fmaf(dm0, f.y, acc[1]);
            f = __half22float2(*reinterpret_cast<__half2*>(&u0.y));
            acc[2] = fmaf(dm0, f.x, acc[2]); acc[3] = fmaf(dm0, f.y, acc[3]);
            f = __half22float2(*reinterpret_cast<__half2*>(&u0.z));
            acc[4] = fmaf(dm0, f.x, acc[4]); acc[5] = fmaf(dm0, f.y, acc[5]);
            f = __half22float2(*reinterpret_cast<__half2*>(&u0.w));
            acc[6] = fmaf(dm0, f.x, acc[6]); acc[7] = fmaf(dm0, f.y, acc[7]);
            f = __half22float2(*reinterpret_cast<__half2*>(&u1.x));
            acc[0] = fmaf(dm1, f.x, acc[0]); acc[1] = fmaf(dm1, f.y, acc[1]);
            f = __half22float2(*reinterpret_cast<__half2*>(&u1.y));
            acc[2] = fmaf(dm1, f.x, acc[2]); acc[3] = fmaf(dm1, f.y, acc[3]);
            f = __half22float2(*reinterpret_cast<__half2*>(&u1.z));
            acc[4] = fmaf(dm1, f.x, acc[4]); acc[5] = fmaf(dm1, f.y, acc[5]);
            f = __half22float2(*reinterpret_cast<__half2*>(&u1.w));
            acc[6] = fmaf(dm1, f.x, acc[6]); acc[7] = fmaf(dm1, f.y, acc[7]);
        }

        if (grp == 0) {   // self loop
            float selfs = ROWDINV ? d_dinv[node] : 1.f;
            uint4 su = gh4[node * 8 + sub];
            float2 f;
            f = __half22float2(*reinterpret_cast<__half2*>(&su.x));
            acc[0] = fmaf(selfs, f.x, acc[0]); acc[1] = fmaf(selfs, f.y, acc[1]);
            f = __half22float2(*reinterpret_cast<__half2*>(&su.y));
            acc[2] = fmaf(selfs, f.x, acc[2]); acc[3] = fmaf(selfs, f.y, acc[3]);
            f = __half22float2(*reinterpret_cast<__half2*>(&su.z));
            acc[4] = fmaf(selfs, f.x, acc[4]); acc[5] = fmaf(selfs, f.y, acc[5]);
            f = __half22float2(*reinterpret_cast<__half2*>(&su.w));
            acc[6] = fmaf(selfs, f.x, acc[6]); acc[7] = fmaf(selfs, f.y, acc[7]);
        }
    }

#pragma unroll
    for (int i = 0; i < 8; i++) acc[i] += __shfl_xor_sync(0xffffffffu, acc[i], 8);
#pragma unroll
    for (int i = 0; i < 8; i++) acc[i] += __shfl_xor_sync(0xffffffffu, acc[i], 16);

    float dv = (node < N_NODES) ? d_dinv[node] : 0.f;
#pragma unroll
    for (int i = 0; i < 8; i++) acc[i] *= dv;

    if (grp == 0) {
        if (node < N_NODES) {
            float4 o0 = make_float4(acc[0], acc[1], acc[2], acc[3]);
            float4 o1 = make_float4(acc[4], acc[5], acc[6], acc[7]);
            *reinterpret_cast<float4*>(&d_acc[node * 64 + sub * 8])     = o0;
            *reinterpret_cast<float4*>(&d_acc[node * 64 + sub * 8 + 4]) = o1;
        }
#pragma unroll
        for (int i = 0; i < 8; i++) {
            ssum[w * 65 + sub * 8 + i] = (node < N_NODES) ? acc[i] : 0.f;
            ssq [w * 65 + sub * 8 + i] = (node < N_NODES) ? acc[i] * acc[i] : 0.f;
        }
    }
    __syncthreads();
    if (threadIdx.x < 128) {
        int feat = threadIdx.x & 63;
        bool isq = threadIdx.x >= 64;
        const float* src = isq ? ssq : ssum;
        float a = 0.f;
#pragma unroll
        for (int ww = 0; ww < 16; ww++) a += src[ww * 65 + feat];
        atomicAdd(&d_stat[L * 128 + (isq ? 64 : 0) + feat], a);
    }
}

// ---------------- fused pool + fc1 ----------------
__global__ void k_poolfc1(const float* __restrict__ g, const float* __restrict__ be,
                          const float* __restrict__ W1) {
    __shared__ float sS[64], sT[64];
    __shared__ float sp[8 * 64];
    __shared__ float sq1[8 * 65], sq2[8 * 65];
    bn_to_smem(2, g, be, (float)N_NODES, sS, sT);

    const int w = threadIdx.x >> 5;
    const int lane = threadIdx.x & 31;
    const int gbase = blockIdx.x * 8;
    const int gidx = gbase + w;
    {
        const int s = d_goff[gidx];
        const int e = d_goff[gidx + 1];
        const int half = lane >> 4;
        const int chunk = lane & 15;
        float4 a = make_float4(0.f, 0.f, 0.f, 0.f);
        for (int n = s + half; n < e; n += 2) {
            float4 v = *reinterpret_cast<const float4*>(&d_acc[n * 64 + chunk * 4]);
            a.x += fmaxf(fmaf(v.x, sS[chunk * 4 + 0], sT[chunk * 4 + 0]), 0.f);
            a.y += fmaxf(fmaf(v.y, sS[chunk * 4 + 1], sT[chunk * 4 + 1]), 0.f);
            a.z += fmaxf(fmaf(v.z, sS[chunk * 4 + 2], sT[chunk * 4 + 2]), 0.f);
            a.w += fmaxf(fmaf(v.w, sS[chunk * 4 + 3], sT[chunk * 4 + 3]), 0.f);
        }
        a.x += __shfl_xor_sync(0xffffffffu, a.x, 16);
        a.y += __shfl_xor_sync(0xffffffffu, a.y, 16);
        a.z += __shfl_xor_sync(0xffffffffu, a.z, 16);
        a.w += __shfl_xor_sync(0xffffffffu, a.w, 16);
        if (half == 0) {
            float inv = 1.0f / fmaxf((float)(e - s), 1.0f);
            float4 o = make_float4(a.x * inv, a.y * inv, a.z * inv, a.w * inv);
            *reinterpret_cast<float4*>(&sp[w * 64 + chunk * 4]) = o;
        }
    }
    __syncthreads();

    const int f = threadIdx.x & 63;
    const int g0 = threadIdx.x >> 6;
#pragma unroll
    for (int pass = 0; pass < 2; pass++) {
        int gg = g0 + pass * 4;
        float q = 0.f;
        const float* pv = &sp[gg * 64];
#pragma unroll 8
        for (int k = 0; k < 64; k++)
            q = fmaf(pv[k], __ldg(&W1[k * 64 + f]), q);
        d_q[(gbase + gg) * 64 + f] = q;
        sq1[gg * 65 + f] = q;
        sq2[gg * 65 + f] = q * q;
    }
    __syncthreads();
    if (threadIdx.x < 128) {
        int feat = threadIdx.x & 63;
        bool isq = threadIdx.x >= 64;
        const float* src = isq ? sq2 : sq1;
        float a = 0.f;
#pragma unroll
        for (int gg = 0; gg < 8; gg++) a += src[gg * 65 + feat];
        atomicAdd(&d_stat[3 * 128 + (isq ? 64 : 0) + feat], a);
    }
}

__global__ void k_fc2(const float* __restrict__ W2, const float* __restrict__ b2,
                      const float* __restrict__ gf, const float* __restrict__ bf,
                      float* __restrict__ out) {
    __shared__ float sS[64], sT[64];
    bn_to_smem(3, gf, bf, (float)N_GRAPHS, sS, sT);
    int g = blockIdx.x * (blockDim.x / 32) + (threadIdx.x >> 5);
    int lane = threadIdx.x & 31;
    if (g >= N_GRAPHS) return;
    float acc = 0.f;
#pragma unroll
    for (int j = 0; j < 2; j++) {
        int f = lane + 32 * j;
        float z = fmaxf(fmaf(d_q[g * 64 + f], sS[f], sT[f]), 0.f);
        acc = fmaf(z, W2[f], acc);
    }
#pragma unroll
    for (int o = 16; o > 0; o >>= 1)
        acc += __shfl_down_sync(0xffffffffu, acc, o);
    if (lane == 0) out[g] = acc + b2[0];
}

// ---------------- launch ----------------
extern "C" void kernel_launch(void* const* d_in, const int* in_sizes, int n_in,
                              void* d_out, int out_size) {
    const float* x     = (const float*)d_in[0];
    const int*   ei    = (const int*)d_in[1];
    const int*   row   = ei;
    const int*   col   = ei + N_EDGES;
    const int*   batch = (const int*)d_in[2];
    const float* Wc0 = (const float*)d_in[3];
    const float* g0  = (const float*)d_in[5];
    const float* be0 = (const float*)d_in[6];
    const float* Wc1 = (const float*)d_in[7];
    const float* g1  = (const float*)d_in[9];
    const float* be1 = (const float*)d_in[10];
    const float* Wc2 = (const float*)d_in[11];
    const float* g2  = (const float*)d_in[13];
    const float* be2 = (const float*)d_in[14];
    const float* W1  = (const float*)d_in[15];
    const float* gf  = (const float*)d_in[17];
    const float* bf  = (const float*)d_in[18];
    const float* W2  = (const float*)d_in[19];
    const float* b2  = (const float*)d_in[20];
    float* out = (float*)d_out;

    static cudaStream_t s1 = nullptr;
    static cudaEvent_t eFork = nullptr, eGemm0 = nullptr;
    static void* deg4Addr = nullptr;
    if (s1 == nullptr) {
        cudaStreamCreateWithFlags(&s1, cudaStreamNonBlocking);
        cudaEventCreateWithFlags(&eFork, cudaEventDisableTiming);
        cudaEventCreateWithFlags(&eGemm0, cudaEventDisableTiming);
        cudaGetSymbolAddress(&deg4Addr, d_deg4);
    }

    const int GEMM_GRID = (N_NODES + 63) / 64;              // 1563
    const int AGGR_GRID = (N_NODES + 15) / 16;              // 6250
    const int N256 = (N_NODES + 255) / 256;                 // 391

    // Side stream: zero stats, graph offsets, GEMM0 (graph-structure-free)
    cudaEventRecord(eFork, 0);
    cudaStreamWaitEvent(s1, eFork, 0);
    k_zero<<<2, 256, 0, s1>>>();
    k_goff<<<(N_GRAPHS + 256) / 256, 256, 0, s1>>>(batch);
    k_gemm0<<<GEMM_GRID, 256, 0, s1>>>(x, Wc0);
    cudaEventRecord(eGemm0, s1);

    // Critical path: packed padded CSR build (R13-proven, 4-way deg)
    cudaMemsetAsync(deg4Addr, 0, 4 * N_NODES * sizeof(int), 0);
    k_deg <<<8192, 256>>>(col);
    k_scanA<<<NBLK, SCAN_B>>>();
    k_scanC2<<<N256, 256>>>();
    k_fill<<<8192, 256>>>(row, col);

    cudaStreamWaitEvent(0, eGemm0, 0);

    // layer 0
    k_aggr4<true><<<AGGR_GRID, 512>>>(0);
    // layer 1 (tf32 MMA GEMM)
    k_gemm_tf32<<<GEMM_GRID, 256>>>(Wc1, 0, g0, be0);
    k_aggr4<false><<<AGGR_GRID, 512>>>(1);
    // layer 2
    k_gemm_tf32<<<GEMM_GRID, 256>>>(Wc2, 1, g1, be1);
    k_aggr4<false><<<AGGR_GRID, 512>>>(2);

    // pooling + head (pool/fc1 fused)
    k_poolfc1<<<N_GRAPHS / 8, 256>>>(g2, be2, W1);
    k_fc2<<<N_GRAPHS / 8, 256>>>(W2, b2, gf, bf, out);
}

// round 16
// speedup vs baseline: 1.0482x; 1.0213x over previous
#include <cuda_runtime.h>
#include <cuda_fp16.h>

#define N_NODES 100000
#define N_EDGES 3200000
#define N_GRAPHS 4096
#define IN_DIM 128
#define HID 64
#define EPS 1e-5f

#define SCAN_B 512
#define NBLK ((N_NODES + SCAN_B - 1) / SCAN_B)   // 196
#define CSR_CAP (N_EDGES + 8 * N_NODES)

// ---------------- scratch (device globals; no allocation) ----------------
__device__ __half2 d_gh [(N_NODES + 1) * 32];    // sentinel row at N_NODES (zeros)
__device__ float   d_acc[N_NODES * HID];
__device__ int     d_deg [N_NODES];              // combined in-degree
__device__ int     d_deg4[4 * N_NODES];          // 4-way sub-histograms (self-cleaning)
__device__ float   d_dinv[N_NODES + 1];
__device__ int     d_off [N_NODES];
__device__ int     d_cur [N_NODES];
__device__ int     d_bsum[NBLK];
__device__ int     d_csr [CSR_CAP];
__device__ float   d_stat[4 * 2 * HID];
__device__ int     d_goff[N_GRAPHS + 1];
__device__ float   d_q   [N_GRAPHS * HID];

__device__ __forceinline__ void bn_to_smem(int L, const float* g, const float* be,
                                           float cnt, float* sS, float* sT) {
    if (threadIdx.x < 64) {
        int f = threadIdx.x;
        float mean = d_stat[L * 128 + f] / cnt;
        float var  = d_stat[L * 128 + 64 + f] / cnt - mean * mean;
        var = fmaxf(var, 0.f);
        float s = g[f] * rsqrtf(var + EPS);
        sS[f] = s;
        sT[f] = be[f] - mean * s;
    }
    __syncthreads();
}

__device__ __forceinline__ unsigned f2tf32(float v) {
    unsigned u;
    asm("cvt.rna.tf32.f32 %0, %1;" : "=r"(u) : "f"(v));
    return u;
}

__device__ __forceinline__ void mma_tf32(float c[4], unsigned a0, unsigned a1,
                                         unsigned a2, unsigned a3,
                                         unsigned b0, unsigned b1) {
    asm volatile(
        "mma.sync.aligned.m16n8k8.row.col.f32.tf32.tf32.f32 "
        "{%0,%1,%2,%3}, {%4,%5,%6,%7}, {%8,%9}, {%0,%1,%2,%3};"
        : "+f"(c[0]), "+f"(c[1]), "+f"(c[2]), "+f"(c[3])
        : "r"(a0), "r"(a1), "r"(a2), "r"(a3), "r"(b0), "r"(b1));
}

// ---------------- setup kernels ----------------
__global__ void k_zero() {
    int i = blockIdx.x * blockDim.x + threadIdx.x;
    if (i < 4 * 2 * HID) d_stat[i] = 0.f;
}

__global__ void k_goff(const int* __restrict__ batch) {
    int g = blockIdx.x * blockDim.x + threadIdx.x;
    if (g > N_GRAPHS) return;
    int lo = 0, hi = N_NODES;
    while (lo < hi) {
        int mid = (lo + hi) >> 1;
        if (batch[mid] < g) lo = mid + 1; else hi = mid;
    }
    d_goff[g] = lo;
}

// 4-way sub-histogram degree count (one edge per thread)
__global__ void k_deg(const int* __restrict__ col) {
    int e = blockIdx.x * blockDim.x + threadIdx.x;
    if (e >= N_EDGES) return;
    int* hist = d_deg4 + (blockIdx.x & 3) * N_NODES;
    atomicAdd(&hist[col[e]], 1);
}

// scan of PADDED in-degree: sums 4 histograms, writes combined deg,
// and ZEROES the histograms for the next graph replay (self-cleaning).
__global__ void k_scanA() {
    __shared__ int s[SCAN_B];
    int i = blockIdx.x * SCAN_B + threadIdx.x;
    int v = 0;
    if (i < N_NODES) {
        int e = d_deg4[i] + d_deg4[N_NODES + i]
              + d_deg4[2 * N_NODES + i] + d_deg4[3 * N_NODES + i];
        d_deg4[i] = 0;
        d_deg4[N_NODES + i] = 0;
        d_deg4[2 * N_NODES + i] = 0;
        d_deg4[3 * N_NODES + i] = 0;
        d_deg[i] = e;
        v = (e + 7) & ~7;
    }
    s[threadIdx.x] = v;
    __syncthreads();
    for (int off = 1; off < SCAN_B; off <<= 1) {
        int t = (threadIdx.x >= off) ? s[threadIdx.x - off] : 0;
        __syncthreads();
        s[threadIdx.x] += t;
        __syncthreads();
    }
    if (i < N_NODES) d_off[i] = s[threadIdx.x] - v;
    if (threadIdx.x == SCAN_B - 1) d_bsum[blockIdx.x] = s[SCAN_B - 1];
}

// fused scanB + scanC + dinv + sentinel-pad writes
__global__ void k_scanC2() {
    __shared__ int sred[256];
    int sb = blockIdx.x >> 1;
    int v = (threadIdx.x < sb) ? d_bsum[threadIdx.x] : 0;
    sred[threadIdx.x] = v;
    __syncthreads();
#pragma unroll
    for (int off = 128; off > 0; off >>= 1) {
        if (threadIdx.x < off) sred[threadIdx.x] += sred[threadIdx.x + off];
        __syncthreads();
    }
    int pref = sred[0];
    int i = blockIdx.x * 256 + threadIdx.x;
    if (i < N_NODES) {
        int o = d_off[i] + pref;
        int e = d_deg[i];
        d_off[i] = o;
        d_cur[i] = o;
        d_dinv[i] = rsqrtf((float)(e + 1));      // +1 self loop
        int padlen = (e + 7) & ~7;
        for (int k = e; k < padlen; k++) d_csr[o + k] = N_NODES;
    }
    if (blockIdx.x == 0 && threadIdx.x == 0) d_dinv[N_NODES] = 0.f;
}

// CSR fill (one edge per thread)
__global__ void k_fill(const int* __restrict__ row, const int* __restrict__ col) {
    int e = blockIdx.x * blockDim.x + threadIdx.x;
    if (e >= N_EDGES) return;
    int pos = atomicAdd(&d_cur[col[e]], 1);
    d_csr[pos] = row[e];
}

// ---------------- GEMM0 (layer 0, FFMA, side stream) ----------------
__global__ void k_gemm0(const float* __restrict__ in, const float* __restrict__ W) {
    __shared__ float sW[64 * 64];
    __shared__ float sX[64 * 68];
    const int tr = threadIdx.x & 15;
    const int tc = threadIdx.x >> 4;
    const int base = blockIdx.x * 64;

    float acc[4][4];
#pragma unroll
    for (int i = 0; i < 4; i++)
#pragma unroll
        for (int j = 0; j < 4; j++) acc[i][j] = 0.f;

    for (int kt = 0; kt < 2; kt++) {
        for (int i = threadIdx.x; i < 4096; i += 256)
            sW[i] = W[kt * 4096 + i];
        for (int i = threadIdx.x; i < 4096; i += 256) {
            int n = i >> 6, k = i & 63;
            int ng = base + n;
            sX[k * 68 + n] = (ng < N_NODES) ? in[ng * 128 + kt * 64 + k] : 0.f;
        }
        __syncthreads();
#pragma unroll 8
        for (int kk = 0; kk < 64; kk++) {
            float4 xv = *reinterpret_cast<float4*>(&sX[kk * 68 + tr * 4]);
            float4 wv = *reinterpret_cast<float4*>(&sW[kk * 64 + tc * 4]);
            acc[0][0] = fmaf(xv.x, wv.x, acc[0][0]);
            acc[0][1] = fmaf(xv.x, wv.y, acc[0][1]);
            acc[0][2] = fmaf(xv.x, wv.z, acc[0][2]);
            acc[0][3] = fmaf(xv.x, wv.w, acc[0][3]);
            acc[1][0] = fmaf(xv.y, wv.x, acc[1][0]);
            acc[1][1] = fmaf(xv.y, wv.y, acc[1][1]);
            acc[1][2] = fmaf(xv.y, wv.z, acc[1][2]);
            acc[1][3] = fmaf(xv.y, wv.w, acc[1][3]);
            acc[2][0] = fmaf(xv.z, wv.x, acc[2][0]);
            acc[2][1] = fmaf(xv.z, wv.y, acc[2][1]);
            acc[2][2] = fmaf(xv.z, wv.z, acc[2][2]);
            acc[2][3] = fmaf(xv.z, wv.w, acc[2][3]);
            acc[3][0] = fmaf(xv.w, wv.x, acc[3][0]);
            acc[3][1] = fmaf(xv.w, wv.y, acc[3][1]);
            acc[3][2] = fmaf(xv.w, wv.z, acc[3][2]);
            acc[3][3] = fmaf(xv.w, wv.w, acc[3][3]);
        }
        __syncthreads();
    }
#pragma unroll
    for (int i = 0; i < 4; i++) {
        int n = base + tr * 4 + i;
        if (n < N_NODES) {
            __half2 h0 = __floats2half2_rn(acc[i][0], acc[i][1]);
            __half2 h1 = __floats2half2_rn(acc[i][2], acc[i][3]);
            uint2 u;
            u.x = *reinterpret_cast<unsigned*>(&h0);
            u.y = *reinterpret_cast<unsigned*>(&h1);
            *reinterpret_cast<uint2*>(&d_gh[n * 32 + tc * 2]) = u;
        }
    }
}

// ---------------- tf32 MMA GEMM (layers 1,2) ----------------
__global__ void k_gemm_tf32(const float* __restrict__ W, int stL,
                            const float* __restrict__ g, const float* __restrict__ be) {
    __shared__ unsigned sA[64 * 68];
    __shared__ unsigned sB[64 * 68];
    __shared__ float sS[64], sT[64];
    const int base = blockIdx.x * 64;

    bn_to_smem(stL, g, be, (float)N_NODES, sS, sT);

    for (int i = threadIdx.x; i < 4096; i += 256) {
        int k = i >> 6, f = i & 63;
        sB[k * 68 + f] = f2tf32(W[i]);
    }
    for (int i = threadIdx.x; i < 4096; i += 256) {
        int m = i >> 6, k = i & 63;
        int ng = base + m;
        float v = 0.f;
        if (ng < N_NODES)
            v = fmaxf(fmaf(d_acc[ng * 64 + k], sS[k], sT[k]), 0.f);
        sA[m * 68 + k] = f2tf32(v);
    }
    __syncthreads();

    const int wid = threadIdx.x >> 5;
    const int lane = threadIdx.x & 31;
    const int gid = lane >> 2;
    const int tig = lane & 3;
    const int wm = (wid & 3) * 16;
    const int wn = (wid >> 2) * 32;

    float c[4][4];
#pragma unroll
    for (int nn = 0; nn < 4; nn++)
#pragma unroll
        for (int i = 0; i < 4; i++) c[nn][i] = 0.f;

#pragma unroll
    for (int k0 = 0; k0 < 64; k0 += 8) {
        unsigned a0 = sA[(wm + gid) * 68 + k0 + tig];
        unsigned a1 = sA[(wm + gid + 8) * 68 + k0 + tig];
        unsigned a2 = sA[(wm + gid) * 68 + k0 + tig + 4];
        unsigned a3 = sA[(wm + gid + 8) * 68 + k0 + tig + 4];
#pragma unroll
        for (int nn = 0; nn < 4; nn++) {
            unsigned b0 = sB[(k0 + tig) * 68 + wn + nn * 8 + gid];
            unsigned b1 = sB[(k0 + tig + 4) * 68 + wn + nn * 8 + gid];
            mma_tf32(c[nn], a0, a1, a2, a3, b0, b1);
        }
    }

    int n0 = base + wm + gid;
    int n1 = n0 + 8;
    float dv0 = (n0 < N_NODES) ? d_dinv[n0] : 0.f;
    float dv1 = (n1 < N_NODES) ? d_dinv[n1] : 0.f;
#pragma unroll
    for (int nn = 0; nn < 4; nn++) {
        int f = wn + nn * 8 + 2 * tig;
        if (n0 < N_NODES)
            d_gh[n0 * 32 + (f >> 1)] = __floats2half2_rn(c[nn][0] * dv0, c[nn][1] * dv0);
        if (n1 < N_NODES)
            d_gh[n1 * 32 + (f >> 1)] = __floats2half2_rn(c[nn][2] * dv1, c[nn][3] * dv1);
    }
}

// ---------------- branchless padded-CSR gather-aggregate (R13-proven) -------
template <bool ROWDINV>
__global__ void k_aggr4(int L) {
    __shared__ float ssum[16 * 65];
    __shared__ float ssq [16 * 65];
    const int w = threadIdx.x >> 5;
    const int lane = threadIdx.x & 31;
    const int grp = lane >> 3;
    const int sub = lane & 7;
    const int node = blockIdx.x * 16 + w;
    const uint4* __restrict__ gh4 = reinterpret_cast<const uint4*>(d_gh);

    float acc[8];
#pragma unroll
    for (int i = 0; i < 8; i++) acc[i] = 0.f;

    if (node < N_NODES) {
        const int start = d_off[node];
        const int e = d_deg[node];
        const int padlen = (e + 7) & ~7;

        for (int j = 0; j < padlen; j += 8) {
            int r0 = __ldg(&d_csr[start + j + grp]);
            int r1 = __ldg(&d_csr[start + j + 4 + grp]);
            uint4 u0 = __ldg(&gh4[r0 * 8 + sub]);
            uint4 u1 = __ldg(&gh4[r1 * 8 + sub]);
            float dm0 = 1.f, dm1 = 1.f;
            if (ROWDINV) { dm0 = __ldg(&d_dinv[r0]); dm1 = __ldg(&d_dinv[r1]); }
            float2 f;
            f = __half22float2(*reinterpret_cast<__half2*>(&u0.x));
            acc[0] = fmaf(dm0, f.x, acc[0]); acc[1] = fmaf(dm0, f.y, acc[1]);
            f = __half22float2(*reinterpret_cast<__half2*>(&u0.y));
            acc[2] = fmaf(dm0, f.x, acc[2]); acc[3] = fmaf(dm0, f.y, acc[3]);
            f = __half22float2(*reinterpret_cast<__half2*>(&u0.z));
            acc[4] = fmaf(dm0, f.x, acc[4]); acc[5] = fmaf(dm0, f.y, acc[5]);
            f = __half22float2(*reinterpret_cast<__half2*>(&u0.w));
            acc[6] = fmaf(dm0, f.x, acc[6]); acc[7] = fmaf(dm0, f.y, acc[7]);
            f = __half22float2(*reinterpret_cast<__half2*>(&u1.x));
            acc[0] = fmaf(dm1, f.x, acc[0]); acc[1] = fmaf(dm1, f.y, acc[1]);
            f = __half22float2(*reinterpret_cast<__half2*>(&u1.y));
            acc[2] = fmaf(dm1, f.x, acc[2]); acc[3] = fmaf(dm1, f.y, acc[3]);
            f = __half22float2(*reinterpret_cast<__half2*>(&u1.z));
            acc[4] = fmaf(dm1, f.x, acc[4]); acc[5] = fmaf(dm1, f.y, acc[5]);
            f = __half22float2(*reinterpret_cast<__half2*>(&u1.w));
            acc[6] = fmaf(dm1, f.x, acc[6]); acc[7] = fmaf(dm1, f.y, acc[7]);
        }

        if (grp == 0) {   // self loop
            float selfs = ROWDINV ? d_dinv[node] : 1.f;
            uint4 su = gh4[node * 8 + sub];
            float2 f;
            f = __half22float2(*reinterpret_cast<__half2*>(&su.x));
            acc[0] = fmaf(selfs, f.x, acc[0]); acc[1] = fmaf(selfs, f.y, acc[1]);
            f = __half22float2(*reinterpret_cast<__half2*>(&su.y));
            acc[2] = fmaf(selfs, f.x, acc[2]); acc[3] = fmaf(selfs, f.y, acc[3]);
            f = __half22float2(*reinterpret_cast<__half2*>(&su.z));
            acc[4] = fmaf(selfs, f.x, acc[4]); acc[5] = fmaf(selfs, f.y, acc[5]);
            f = __half22float2(*reinterpret_cast<__half2*>(&su.w));
            acc[6] = fmaf(selfs, f.x, acc[6]); acc[7] = fmaf(selfs, f.y, acc[7]);
        }
    }

#pragma unroll
    for (int i = 0; i < 8; i++) acc[i] += __shfl_xor_sync(0xffffffffu, acc[i], 8);
#pragma unroll
    for (int i = 0; i < 8; i++) acc[i] += __shfl_xor_sync(0xffffffffu, acc[i], 16);

    float dv = (node < N_NODES) ? d_dinv[node] : 0.f;
#pragma unroll
    for (int i = 0; i < 8; i++) acc[i] *= dv;

    if (grp == 0) {
        if (node < N_NODES) {
            float4 o0 = make_float4(acc[0], acc[1], acc[2], acc[3]);
            float4 o1 = make_float4(acc[4], acc[5], acc[6], acc[7]);
            *reinterpret_cast<float4*>(&d_acc[node * 64 + sub * 8])     = o0;
            *reinterpret_cast<float4*>(&d_acc[node * 64 + sub * 8 + 4]) = o1;
        }
#pragma unroll
        for (int i = 0; i < 8; i++) {
            ssum[w * 65 + sub * 8 + i] = (node < N_NODES) ? acc[i] : 0.f;
            ssq [w * 65 + sub * 8 + i] = (node < N_NODES) ? acc[i] * acc[i] : 0.f;
        }
    }
    __syncthreads();
    if (threadIdx.x < 128) {
        int feat = threadIdx.x & 63;
        bool isq = threadIdx.x >= 64;
        const float* src = isq ? ssq : ssum;
        float a = 0.f;
#pragma unroll
        for (int ww = 0; ww < 16; ww++) a += src[ww * 65 + feat];
        atomicAdd(&d_stat[L * 128 + (isq ? 64 : 0) + feat], a);
    }
}

// ---------------- fused pool + fc1 ----------------
__global__ void k_poolfc1(const float* __restrict__ g, const float* __restrict__ be,
                          const float* __restrict__ W1) {
    __shared__ float sS[64], sT[64];
    __shared__ float sp[8 * 64];
    __shared__ float sq1[8 * 65], sq2[8 * 65];
    bn_to_smem(2, g, be, (float)N_NODES, sS, sT);

    const int w = threadIdx.x >> 5;
    const int lane = threadIdx.x & 31;
    const int gbase = blockIdx.x * 8;
    const int gidx = gbase + w;
    {
        const int s = d_goff[gidx];
        const int e = d_goff[gidx + 1];
        const int half = lane >> 4;
        const int chunk = lane & 15;
        float4 a = make_float4(0.f, 0.f, 0.f, 0.f);
        for (int n = s + half; n < e; n += 2) {
            float4 v = *reinterpret_cast<const float4*>(&d_acc[n * 64 + chunk * 4]);
            a.x += fmaxf(fmaf(v.x, sS[chunk * 4 + 0], sT[chunk * 4 + 0]), 0.f);
            a.y += fmaxf(fmaf(v.y, sS[chunk * 4 + 1], sT[chunk * 4 + 1]), 0.f);
            a.z += fmaxf(fmaf(v.z, sS[chunk * 4 + 2], sT[chunk * 4 + 2]), 0.f);
            a.w += fmaxf(fmaf(v.w, sS[chunk * 4 + 3], sT[chunk * 4 + 3]), 0.f);
        }
        a.x += __shfl_xor_sync(0xffffffffu, a.x, 16);
        a.y += __shfl_xor_sync(0xffffffffu, a.y, 16);
        a.z += __shfl_xor_sync(0xffffffffu, a.z, 16);
        a.w += __shfl_xor_sync(0xffffffffu, a.w, 16);
        if (half == 0) {
            float inv = 1.0f / fmaxf((float)(e - s), 1.0f);
            float4 o = make_float4(a.x * inv, a.y * inv, a.z * inv, a.w * inv);
            *reinterpret_cast<float4*>(&sp[w * 64 + chunk * 4]) = o;
        }
    }
    __syncthreads();

    const int f = threadIdx.x & 63;
    const int g0 = threadIdx.x >> 6;
#pragma unroll
    for (int pass = 0; pass < 2; pass++) {
        int gg = g0 + pass * 4;
        float q = 0.f;
        const float* pv = &sp[gg * 64];
#pragma unroll 8
        for (int k = 0; k < 64; k++)
            q = fmaf(pv[k], __ldg(&W1[k * 64 + f]), q);
        d_q[(gbase + gg) * 64 + f] = q;
        sq1[gg * 65 + f] = q;
        sq2[gg * 65 + f] = q * q;
    }
    __syncthreads();
    if (threadIdx.x < 128) {
        int feat = threadIdx.x & 63;
        bool isq = threadIdx.x >= 64;
        const float* src = isq ? sq2 : sq1;
        float a = 0.f;
#pragma unroll
        for (int gg = 0; gg < 8; gg++) a += src[gg * 65 + feat];
        atomicAdd(&d_stat[3 * 128 + (isq ? 64 : 0) + feat], a);
    }
}

__global__ void k_fc2(const float* __restrict__ W2, const float* __restrict__ b2,
                      const float* __restrict__ gf, const float* __restrict__ bf,
                      float* __restrict__ out) {
    __shared__ float sS[64], sT[64];
    bn_to_smem(3, gf, bf, (float)N_GRAPHS, sS, sT);
    int g = blockIdx.x * (blockDim.x / 32) + (threadIdx.x >> 5);
    int lane = threadIdx.x & 31;
    if (g >= N_GRAPHS) return;
    float acc = 0.f;
#pragma unroll
    for (int j = 0; j < 2; j++) {
        int f = lane + 32 * j;
        float z = fmaxf(fmaf(d_q[g * 64 + f], sS[f], sT[f]), 0.f);
        acc = fmaf(z, W2[f], acc);
    }
#pragma unroll
    for (int o = 16; o > 0; o >>= 1)
        acc += __shfl_down_sync(0xffffffffu, acc, o);
    if (lane == 0) out[g] = acc + b2[0];
}

// ---------------- launch ----------------
extern "C" void kernel_launch(void* const* d_in, const int* in_sizes, int n_in,
                              void* d_out, int out_size) {
    const float* x     = (const float*)d_in[0];
    const int*   ei    = (const int*)d_in[1];
    const int*   row   = ei;
    const int*   col   = ei + N_EDGES;
    const int*   batch = (const int*)d_in[2];
    const float* Wc0 = (const float*)d_in[3];
    const float* g0  = (const float*)d_in[5];
    const float* be0 = (const float*)d_in[6];
    const float* Wc1 = (const float*)d_in[7];
    const float* g1  = (const float*)d_in[9];
    const float* be1 = (const float*)d_in[10];
    const float* Wc2 = (const float*)d_in[11];
    const float* g2  = (const float*)d_in[13];
    const float* be2 = (const float*)d_in[14];
    const float* W1  = (const float*)d_in[15];
    const float* gf  = (const float*)d_in[17];
    const float* bf  = (const float*)d_in[18];
    const float* W2  = (const float*)d_in[19];
    const float* b2  = (const float*)d_in[20];
    float* out = (float*)d_out;

    static cudaStream_t s1 = nullptr;
    static cudaEvent_t eFork = nullptr, eGemm0 = nullptr;
    if (s1 == nullptr) {
        cudaStreamCreateWithFlags(&s1, cudaStreamNonBlocking);
        cudaEventCreateWithFlags(&eFork, cudaEventDisableTiming);
        cudaEventCreateWithFlags(&eGemm0, cudaEventDisableTiming);
    }

    const int GEMM_GRID = (N_NODES + 63) / 64;              // 1563
    const int AGGR_GRID = (N_NODES + 15) / 16;              // 6250
    const int N256 = (N_NODES + 255) / 256;                 // 391
    const int EDGE_GRID = (N_EDGES + 255) / 256;            // 12500

    // Side stream: zero stats, graph offsets, GEMM0 (graph-structure-free)
    cudaEventRecord(eFork, 0);
    cudaStreamWaitEvent(s1, eFork, 0);
    k_zero<<<2, 256, 0, s1>>>();
    k_goff<<<(N_GRAPHS + 256) / 256, 256, 0, s1>>>(batch);
    k_gemm0<<<GEMM_GRID, 256, 0, s1>>>(x, Wc0);
    cudaEventRecord(eGemm0, s1);

    // Critical path: packed padded CSR build (R13-proven; histograms are
    // self-cleaning — zeroed by previous run's k_scanA, BSS-zero initially)
    k_deg <<<EDGE_GRID, 256>>>(col);
    k_scanA<<<NBLK, SCAN_B>>>();
    k_scanC2<<<N256, 256>>>();
    k_fill<<<EDGE_GRID, 256>>>(row, col);

    cudaStreamWaitEvent(0, eGemm0, 0);

    // layer 0
    k_aggr4<true><<<AGGR_GRID, 512>>>(0);
    // layer 1 (tf32 MMA GEMM)
    k_gemm_tf32<<<GEMM_GRID, 256>>>(Wc1, 0, g0, be0);
    k_aggr4<false><<<AGGR_GRID, 512>>>(1);
    // layer 2
    k_gemm_tf32<<<GEMM_GRID, 256>>>(Wc2, 1, g1, be1);
    k_aggr4<false><<<AGGR_GRID, 512>>>(2);

    // pooling + head (pool/fc1 fused)
    k_poolfc1<<<N_GRAPHS / 8, 256>>>(g2, be2, W1);
    k_fc2<<<N_GRAPHS / 8, 256>>>(W2, b2, gf, bf, out);
}

// round 17
// speedup vs baseline: 1.0580x; 1.0093x over previous
#include <cuda_runtime.h>
#include <cuda_fp16.h>

#define N_NODES 100000
#define N_EDGES 3200000
#define N_GRAPHS 4096
#define IN_DIM 128
#define HID 64
#define EPS 1e-5f

#define SCAN_B 512
#define NBLK ((N_NODES + SCAN_B - 1) / SCAN_B)   // 196
#define CSR_CAP (N_EDGES + 8 * N_NODES)
#define NSLICE 8                                  // stat accumulator slices

// ---------------- scratch (device globals; no allocation) ----------------
__device__ __half2 d_gh [(N_NODES + 1) * 32];    // sentinel row at N_NODES (zeros)
__device__ float   d_acc[N_NODES * HID];
__device__ int     d_deg [N_NODES];              // combined in-degree
__device__ int     d_deg4[4 * N_NODES];          // 4-way sub-histograms (self-cleaning)
__device__ float   d_dinv[N_NODES + 1];
__device__ int     d_off [N_NODES];
__device__ int     d_cur [N_NODES];
__device__ int     d_bsum[NBLK];
__device__ int     d_csr [CSR_CAP];
__device__ float   d_stat[NSLICE * 4 * 2 * HID]; // 8 slices x (4 layers x 128)
__device__ int     d_goff[N_GRAPHS + 1];
__device__ float   d_q   [N_GRAPHS * HID];

// sums the 8 stat slices for layer L and builds BN scale/shift in smem
__device__ __forceinline__ void bn_to_smem(int L, const float* g, const float* be,
                                           float cnt, float* sS, float* sT) {
    if (threadIdx.x < 64) {
        int f = threadIdx.x;
        float s1 = 0.f, s2 = 0.f;
#pragma unroll
        for (int c = 0; c < NSLICE; c++) {
            s1 += d_stat[c * 512 + L * 128 + f];
            s2 += d_stat[c * 512 + L * 128 + 64 + f];
        }
        float mean = s1 / cnt;
        float var  = s2 / cnt - mean * mean;
        var = fmaxf(var, 0.f);
        float s = g[f] * rsqrtf(var + EPS);
        sS[f] = s;
        sT[f] = be[f] - mean * s;
    }
    __syncthreads();
}

__device__ __forceinline__ unsigned f2tf32(float v) {
    unsigned u;
    asm("cvt.rna.tf32.f32 %0, %1;" : "=r"(u) : "f"(v));
    return u;
}

__device__ __forceinline__ void mma_tf32(float c[4], unsigned a0, unsigned a1,
                                         unsigned a2, unsigned a3,
                                         unsigned b0, unsigned b1) {
    asm volatile(
        "mma.sync.aligned.m16n8k8.row.col.f32.tf32.tf32.f32 "
        "{%0,%1,%2,%3}, {%4,%5,%6,%7}, {%8,%9}, {%0,%1,%2,%3};"
        : "+f"(c[0]), "+f"(c[1]), "+f"(c[2]), "+f"(c[3])
        : "r"(a0), "r"(a1), "r"(a2), "r"(a3), "r"(b0), "r"(b1));
}

// ---------------- setup kernels ----------------
__global__ void k_zero() {
    int i = blockIdx.x * blockDim.x + threadIdx.x;
    if (i < NSLICE * 4 * 2 * HID) d_stat[i] = 0.f;
}

__global__ void k_goff(const int* __restrict__ batch) {
    int g = blockIdx.x * blockDim.x + threadIdx.x;
    if (g > N_GRAPHS) return;
    int lo = 0, hi = N_NODES;
    while (lo < hi) {
        int mid = (lo + hi) >> 1;
        if (batch[mid] < g) lo = mid + 1; else hi = mid;
    }
    d_goff[g] = lo;
}

// 4-way sub-histogram degree count (one edge per thread)
__global__ void k_deg(const int* __restrict__ col) {
    int e = blockIdx.x * blockDim.x + threadIdx.x;
    if (e >= N_EDGES) return;
    int* hist = d_deg4 + (blockIdx.x & 3) * N_NODES;
    atomicAdd(&hist[col[e]], 1);
}

// scan of PADDED in-degree; self-cleaning histograms
__global__ void k_scanA() {
    __shared__ int s[SCAN_B];
    int i = blockIdx.x * SCAN_B + threadIdx.x;
    int v = 0;
    if (i < N_NODES) {
        int e = d_deg4[i] + d_deg4[N_NODES + i]
              + d_deg4[2 * N_NODES + i] + d_deg4[3 * N_NODES + i];
        d_deg4[i] = 0;
        d_deg4[N_NODES + i] = 0;
        d_deg4[2 * N_NODES + i] = 0;
        d_deg4[3 * N_NODES + i] = 0;
        d_deg[i] = e;
        v = (e + 7) & ~7;
    }
    s[threadIdx.x] = v;
    __syncthreads();
    for (int off = 1; off < SCAN_B; off <<= 1) {
        int t = (threadIdx.x >= off) ? s[threadIdx.x - off] : 0;
        __syncthreads();
        s[threadIdx.x] += t;
        __syncthreads();
    }
    if (i < N_NODES) d_off[i] = s[threadIdx.x] - v;
    if (threadIdx.x == SCAN_B - 1) d_bsum[blockIdx.x] = s[SCAN_B - 1];
}

// fused scanB + scanC + dinv + sentinel-pad writes
__global__ void k_scanC2() {
    __shared__ int sred[256];
    int sb = blockIdx.x >> 1;
    int v = (threadIdx.x < sb) ? d_bsum[threadIdx.x] : 0;
    sred[threadIdx.x] = v;
    __syncthreads();
#pragma unroll
    for (int off = 128; off > 0; off >>= 1) {
        if (threadIdx.x < off) sred[threadIdx.x] += sred[threadIdx.x + off];
        __syncthreads();
    }
    int pref = sred[0];
    int i = blockIdx.x * 256 + threadIdx.x;
    if (i < N_NODES) {
        int o = d_off[i] + pref;
        int e = d_deg[i];
        d_off[i] = o;
        d_cur[i] = o;
        d_dinv[i] = rsqrtf((float)(e + 1));      // +1 self loop
        int padlen = (e + 7) & ~7;
        for (int k = e; k < padlen; k++) d_csr[o + k] = N_NODES;
    }
    if (blockIdx.x == 0 && threadIdx.x == 0) d_dinv[N_NODES] = 0.f;
}

// CSR fill (one edge per thread)
__global__ void k_fill(const int* __restrict__ row, const int* __restrict__ col) {
    int e = blockIdx.x * blockDim.x + threadIdx.x;
    if (e >= N_EDGES) return;
    int pos = atomicAdd(&d_cur[col[e]], 1);
    d_csr[pos] = row[e];
}

// ---------------- GEMM0 (layer 0, FFMA, side stream) ----------------
__global__ void k_gemm0(const float* __restrict__ in, const float* __restrict__ W) {
    __shared__ float sW[64 * 64];
    __shared__ float sX[64 * 68];
    const int tr = threadIdx.x & 15;
    const int tc = threadIdx.x >> 4;
    const int base = blockIdx.x * 64;

    float acc[4][4];
#pragma unroll
    for (int i = 0; i < 4; i++)
#pragma unroll
        for (int j = 0; j < 4; j++) acc[i][j] = 0.f;

    for (int kt = 0; kt < 2; kt++) {
        for (int i = threadIdx.x; i < 4096; i += 256)
            sW[i] = W[kt * 4096 + i];
        for (int i = threadIdx.x; i < 4096; i += 256) {
            int n = i >> 6, k = i & 63;
            int ng = base + n;
            sX[k * 68 + n] = (ng < N_NODES) ? in[ng * 128 + kt * 64 + k] : 0.f;
        }
        __syncthreads();
#pragma unroll 8
        for (int kk = 0; kk < 64; kk++) {
            float4 xv = *reinterpret_cast<float4*>(&sX[kk * 68 + tr * 4]);
            float4 wv = *reinterpret_cast<float4*>(&sW[kk * 64 + tc * 4]);
            acc[0][0] = fmaf(xv.x, wv.x, acc[0][0]);
            acc[0][1] = fmaf(xv.x, wv.y, acc[0][1]);
            acc[0][2] = fmaf(xv.x, wv.z, acc[0][2]);
            acc[0][3] = fmaf(xv.x, wv.w, acc[0][3]);
            acc[1][0] = fmaf(xv.y, wv.x, acc[1][0]);
            acc[1][1] = fmaf(xv.y, wv.y, acc[1][1]);
            acc[1][2] = fmaf(xv.y, wv.z, acc[1][2]);
            acc[1][3] = fmaf(xv.y, wv.w, acc[1][3]);
            acc[2][0] = fmaf(xv.z, wv.x, acc[2][0]);
            acc[2][1] = fmaf(xv.z, wv.y, acc[2][1]);
            acc[2][2] = fmaf(xv.z, wv.z, acc[2][2]);
            acc[2][3] = fmaf(xv.z, wv.w, acc[2][3]);
            acc[3][0] = fmaf(xv.w, wv.x, acc[3][0]);
            acc[3][1] = fmaf(xv.w, wv.y, acc[3][1]);
            acc[3][2] = fmaf(xv.w, wv.z, acc[3][2]);
            acc[3][3] = fmaf(xv.w, wv.w, acc[3][3]);
        }
        __syncthreads();
    }
#pragma unroll
    for (int i = 0; i < 4; i++) {
        int n = base + tr * 4 + i;
        if (n < N_NODES) {
            __half2 h0 = __floats2half2_rn(acc[i][0], acc[i][1]);
            __half2 h1 = __floats2half2_rn(acc[i][2], acc[i][3]);
            uint2 u;
            u.x = *reinterpret_cast<unsigned*>(&h0);
            u.y = *reinterpret_cast<unsigned*>(&h1);
            *reinterpret_cast<uint2*>(&d_gh[n * 32 + tc * 2]) = u;
        }
    }
}

// ---------------- tf32 MMA GEMM (layers 1,2) ----------------
__global__ void k_gemm_tf32(const float* __restrict__ W, int stL,
                            const float* __restrict__ g, const float* __restrict__ be) {
    __shared__ unsigned sA[64 * 68];
    __shared__ unsigned sB[64 * 68];
    __shared__ float sS[64], sT[64];
    const int base = blockIdx.x * 64;

    bn_to_smem(stL, g, be, (float)N_NODES, sS, sT);

    for (int i = threadIdx.x; i < 4096; i += 256) {
        int k = i >> 6, f = i & 63;
        sB[k * 68 + f] = f2tf32(W[i]);
    }
    for (int i = threadIdx.x; i < 4096; i += 256) {
        int m = i >> 6, k = i & 63;
        int ng = base + m;
        float v = 0.f;
        if (ng < N_NODES)
            v = fmaxf(fmaf(d_acc[ng * 64 + k], sS[k], sT[k]), 0.f);
        sA[m * 68 + k] = f2tf32(v);
    }
    __syncthreads();

    const int wid = threadIdx.x >> 5;
    const int lane = threadIdx.x & 31;
    const int gid = lane >> 2;
    const int tig = lane & 3;
    const int wm = (wid & 3) * 16;
    const int wn = (wid >> 2) * 32;

    float c[4][4];
#pragma unroll
    for (int nn = 0; nn < 4; nn++)
#pragma unroll
        for (int i = 0; i < 4; i++) c[nn][i] = 0.f;

#pragma unroll
    for (int k0 = 0; k0 < 64; k0 += 8) {
        unsigned a0 = sA[(wm + gid) * 68 + k0 + tig];
        unsigned a1 = sA[(wm + gid + 8) * 68 + k0 + tig];
        unsigned a2 = sA[(wm + gid) * 68 + k0 + tig + 4];
        unsigned a3 = sA[(wm + gid + 8) * 68 + k0 + tig + 4];
#pragma unroll
        for (int nn = 0; nn < 4; nn++) {
            unsigned b0 = sB[(k0 + tig) * 68 + wn + nn * 8 + gid];
            unsigned b1 = sB[(k0 + tig + 4) * 68 + wn + nn * 8 + gid];
            mma_tf32(c[nn], a0, a1, a2, a3, b0, b1);
        }
    }

    int n0 = base + wm + gid;
    int n1 = n0 + 8;
    float dv0 = (n0 < N_NODES) ? d_dinv[n0] : 0.f;
    float dv1 = (n1 < N_NODES) ? d_dinv[n1] : 0.f;
#pragma unroll
    for (int nn = 0; nn < 4; nn++) {
        int f = wn + nn * 8 + 2 * tig;
        if (n0 < N_NODES)
            d_gh[n0 * 32 + (f >> 1)] = __floats2half2_rn(c[nn][0] * dv0, c[nn][1] * dv0);
        if (n1 < N_NODES)
            d_gh[n1 * 32 + (f >> 1)] = __floats2half2_rn(c[nn][2] * dv1, c[nn][3] * dv1);
    }
}

// ---------------- branchless padded-CSR gather-aggregate (R13/R16 core) -----
// Stat atomics now go to slice (blockIdx & 7) of d_stat.
template <bool ROWDINV>
__global__ void k_aggr4(int L) {
    __shared__ float ssum[16 * 65];
    __shared__ float ssq [16 * 65];
    const int w = threadIdx.x >> 5;
    const int lane = threadIdx.x & 31;
    const int grp = lane >> 3;
    const int sub = lane & 7;
    const int node = blockIdx.x * 16 + w;
    const uint4* __restrict__ gh4 = reinterpret_cast<const uint4*>(d_gh);

    float acc[8];
#pragma unroll
    for (int i = 0; i < 8; i++) acc[i] = 0.f;

    if (node < N_NODES) {
        const int start = d_off[node];
        const int e = d_deg[node];
        const int padlen = (e + 7) & ~7;

        for (int j = 0; j < padlen; j += 8) {
            int r0 = __ldg(&d_csr[start + j + grp]);
            int r1 = __ldg(&d_csr[start + j + 4 + grp]);
            uint4 u0 = __ldg(&gh4[r0 * 8 + sub]);
            uint4 u1 = __ldg(&gh4[r1 * 8 + sub]);
            float dm0 = 1.f, dm1 = 1.f;
            if (ROWDINV) { dm0 = __ldg(&d_dinv[r0]); dm1 = __ldg(&d_dinv[r1]); }
            float2 f;
            f = __half22float2(*reinterpret_cast<__half2*>(&u0.x));
            acc[0] = fmaf(dm0, f.x, acc[0]); acc[1] = fmaf(dm0, f.y, acc[1]);
            f = __half22float2(*reinterpret_cast<__half2*>(&u0.y));
            acc[2] = fmaf(dm0, f.x, acc[2]); acc[3] = fmaf(dm0, f.y, acc[3]);
            f = __half22float2(*reinterpret_cast<__half2*>(&u0.z));
            acc[4] = fmaf(dm0, f.x, acc[4]); acc[5] = fmaf(dm0, f.y, acc[5]);
            f = __half22float2(*reinterpret_cast<__half2*>(&u0.w));
            acc[6] = fmaf(dm0, f.x, acc[6]); acc[7] = fmaf(dm0, f.y, acc[7]);
            f = __half22float2(*reinterpret_cast<__half2*>(&u1.x));
            acc[0] = fmaf(dm1, f.x, acc[0]); acc[1] = fmaf(dm1, f.y, acc[1]);
            f = __half22float2(*reinterpret_cast<__half2*>(&u1.y));
            acc[2] = fmaf(dm1, f.x, acc[2]); acc[3] = fmaf(dm1, f.y, acc[3]);
            f = __half22float2(*reinterpret_cast<__half2*>(&u1.z));
            acc[4] = fmaf(dm1, f.x, acc[4]); acc[5] = fmaf(dm1, f.y, acc[5]);
            f = __half22float2(*reinterpret_cast<__half2*>(&u1.w));
            acc[6] = fmaf(dm1, f.x, acc[6]); acc[7] = fmaf(dm1, f.y, acc[7]);
        }

        if (grp == 0) {   // self loop
            float selfs = ROWDINV ? d_dinv[node] : 1.f;
            uint4 su = gh4[node * 8 + sub];
            float2 f;
            f = __half22float2(*reinterpret_cast<__half2*>(&su.x));
            acc[0] = fmaf(selfs, f.x, acc[0]); acc[1] = fmaf(selfs, f.y, acc[1]);
            f = __half22float2(*reinterpret_cast<__half2*>(&su.y));
            acc[2] = fmaf(selfs, f.x, acc[2]); acc[3] = fmaf(selfs, f.y, acc[3]);
            f = __half22float2(*reinterpret_cast<__half2*>(&su.z));
            acc[4] = fmaf(selfs, f.x, acc[4]); acc[5] = fmaf(selfs, f.y, acc[5]);
            f = __half22float2(*reinterpret_cast<__half2*>(&su.w));
            acc[6] = fmaf(selfs, f.x, acc[6]); acc[7] = fmaf(selfs, f.y, acc[7]);
        }
    }

#pragma unroll
    for (int i = 0; i < 8; i++) acc[i] += __shfl_xor_sync(0xffffffffu, acc[i], 8);
#pragma unroll
    for (int i = 0; i < 8; i++) acc[i] += __shfl_xor_sync(0xffffffffu, acc[i], 16);

    float dv = (node < N_NODES) ? d_dinv[node] : 0.f;
#pragma unroll
    for (int i = 0; i < 8; i++) acc[i] *= dv;

    if (grp == 0) {
        if (node < N_NODES) {
            float4 o0 = make_float4(acc[0], acc[1], acc[2], acc[3]);
            float4 o1 = make_float4(acc[4], acc[5], acc[6], acc[7]);
            *reinterpret_cast<float4*>(&d_acc[node * 64 + sub * 8])     = o0;
            *reinterpret_cast<float4*>(&d_acc[node * 64 + sub * 8 + 4]) = o1;
        }
#pragma unroll
        for (int i = 0; i < 8; i++) {
            ssum[w * 65 + sub * 8 + i] = (node < N_NODES) ? acc[i] : 0.f;
            ssq [w * 65 + sub * 8 + i] = (node < N_NODES) ? acc[i] * acc[i] : 0.f;
        }
    }
    __syncthreads();
    if (threadIdx.x < 128) {
        int feat = threadIdx.x & 63;
        bool isq = threadIdx.x >= 64;
        const float* src = isq ? ssq : ssum;
        float a = 0.f;
#pragma unroll
        for (int ww = 0; ww < 16; ww++) a += src[ww * 65 + feat];
        atomicAdd(&d_stat[(blockIdx.x & (NSLICE - 1)) * 512
                          + L * 128 + (isq ? 64 : 0) + feat], a);
    }
}

// ---------------- fused pool + fc1 ----------------
__global__ void k_poolfc1(const float* __restrict__ g, const float* __restrict__ be,
                          const float* __restrict__ W1) {
    __shared__ float sS[64], sT[64];
    __shared__ float sp[8 * 64];
    __shared__ float sq1[8 * 65], sq2[8 * 65];
    bn_to_smem(2, g, be, (float)N_NODES, sS, sT);

    const int w = threadIdx.x >> 5;
    const int lane = threadIdx.x & 31;
    const int gbase = blockIdx.x * 8;
    const int gidx = gbase + w;
    {
        const int s = d_goff[gidx];
        const int e = d_goff[gidx + 1];
        const int half = lane >> 4;
        const int chunk = lane & 15;
        float4 a = make_float4(0.f, 0.f, 0.f, 0.f);
        for (int n = s + half; n < e; n += 2) {
            float4 v = *reinterpret_cast<const float4*>(&d_acc[n * 64 + chunk * 4]);
            a.x += fmaxf(fmaf(v.x, sS[chunk * 4 + 0], sT[chunk * 4 + 0]), 0.f);
            a.y += fmaxf(fmaf(v.y, sS[chunk * 4 + 1], sT[chunk * 4 + 1]), 0.f);
            a.z += fmaxf(fmaf(v.z, sS[chunk * 4 + 2], sT[chunk * 4 + 2]), 0.f);
            a.w += fmaxf(fmaf(v.w, sS[chunk * 4 + 3], sT[chunk * 4 + 3]), 0.f);
        }
        a.x += __shfl_xor_sync(0xffffffffu, a.x, 16);
        a.y += __shfl_xor_sync(0xffffffffu, a.y, 16);
        a.z += __shfl_xor_sync(0xffffffffu, a.z, 16);
        a.w += __shfl_xor_sync(0xffffffffu, a.w, 16);
        if (half == 0) {
            float inv = 1.0f / fmaxf((float)(e - s), 1.0f);
            float4 o = make_float4(a.x * inv, a.y * inv, a.z * inv, a.w * inv);
            *reinterpret_cast<float4*>(&sp[w * 64 + chunk * 4]) = o;
        }
    }
    __syncthreads();

    const int f = threadIdx.x & 63;
    const int g0 = threadIdx.x >> 6;
#pragma unroll
    for (int pass = 0; pass < 2; pass++) {
        int gg = g0 + pass * 4;
        float q = 0.f;
        const float* pv = &sp[gg * 64];
#pragma unroll 8
        for (int k = 0; k < 64; k++)
            q = fmaf(pv[k], __ldg(&W1[k * 64 + f]), q);
        d_q[(gbase + gg) * 64 + f] = q;
        sq1[gg * 65 + f] = q;
        sq2[gg * 65 + f] = q * q;
    }
    __syncthreads();
    if (threadIdx.x < 128) {
        int feat = threadIdx.x & 63;
        bool isq = threadIdx.x >= 64;
        const float* src = isq ? sq2 : sq1;
        float a = 0.f;
#pragma unroll
        for (int gg = 0; gg < 8; gg++) a += src[gg * 65 + feat];
        atomicAdd(&d_stat[(blockIdx.x & (NSLICE - 1)) * 512
                          + 3 * 128 + (isq ? 64 : 0) + feat], a);
    }
}

__global__ void k_fc2(const float* __restrict__ W2, const float* __restrict__ b2,
                      const float* __restrict__ gf, const float* __restrict__ bf,
                      float* __restrict__ out) {
    __shared__ float sS[64], sT[64];
    bn_to_smem(3, gf, bf, (float)N_GRAPHS, sS, sT);
    int g = blockIdx.x * (blockDim.x / 32) + (threadIdx.x >> 5);
    int lane = threadIdx.x & 31;
    if (g >= N_GRAPHS) return;
    float acc = 0.f;
#pragma unroll
    for (int j = 0; j < 2; j++) {
        int f = lane + 32 * j;
        float z = fmaxf(fmaf(d_q[g * 64 + f], sS[f], sT[f]), 0.f);
        acc = fmaf(z, W2[f], acc);
    }
#pragma unroll
    for (int o = 16; o > 0; o >>= 1)
        acc += __shfl_down_sync(0xffffffffu, acc, o);
    if (lane == 0) out[g] = acc + b2[0];
}

// ---------------- launch ----------------
extern "C" void kernel_launch(void* const* d_in, const int* in_sizes, int n_in,
                              void* d_out, int out_size) {
    const float* x     = (const float*)d_in[0];
    const int*   ei    = (const int*)d_in[1];
    const int*   row   = ei;
    const int*   col   = ei + N_EDGES;
    const int*   batch = (const int*)d_in[2];
    const float* Wc0 = (const float*)d_in[3];
    const float* g0  = (const float*)d_in[5];
    const float* be0 = (const float*)d_in[6];
    const float* Wc1 = (const float*)d_in[7];
    const float* g1  = (const float*)d_in[9];
    const float* be1 = (const float*)d_in[10];
    const float* Wc2 = (const float*)d_in[11];
    const float* g2  = (const float*)d_in[13];
    const float* be2 = (const float*)d_in[14];
    const float* W1  = (const float*)d_in[15];
    const float* gf  = (const float*)d_in[17];
    const float* bf  = (const float*)d_in[18];
    const float* W2  = (const float*)d_in[19];
    const float* b2  = (const float*)d_in[20];
    float* out = (float*)d_out;

    static cudaStream_t s1 = nullptr;
    static cudaEvent_t eFork = nullptr, eGemm0 = nullptr;
    if (s1 == nullptr) {
        cudaStreamCreateWithFlags(&s1, cudaStreamNonBlocking);
        cudaEventCreateWithFlags(&eFork, cudaEventDisableTiming);
        cudaEventCreateWithFlags(&eGemm0, cudaEventDisableTiming);
    }

    const int GEMM_GRID = (N_NODES + 63) / 64;              // 1563
    const int AGGR_GRID = (N_NODES + 15) / 16;              // 6250
    const int N256 = (N_NODES + 255) / 256;                 // 391
    const int EDGE_GRID = (N_EDGES + 255) / 256;            // 12500

    // Side stream: zero stat slices, graph offsets, GEMM0
    cudaEventRecord(eFork, 0);
    cudaStreamWaitEvent(s1, eFork, 0);
    k_zero<<<(NSLICE * 512 + 255) / 256, 256, 0, s1>>>();
    k_goff<<<(N_GRAPHS + 256) / 256, 256, 0, s1>>>(batch);
    k_gemm0<<<GEMM_GRID, 256, 0, s1>>>(x, Wc0);
    cudaEventRecord(eGemm0, s1);

    // Critical path: packed padded CSR build (R16 champion chain)
    k_deg <<<EDGE_GRID, 256>>>(col);
    k_scanA<<<NBLK, SCAN_B>>>();
    k_scanC2<<<N256, 256>>>();
    k_fill<<<EDGE_GRID, 256>>>(row, col);

    cudaStreamWaitEvent(0, eGemm0, 0);

    // layer 0
    k_aggr4<true><<<AGGR_GRID, 512>>>(0);
    // layer 1 (tf32 MMA GEMM)
    k_gemm_tf32<<<GEMM_GRID, 256>>>(Wc1, 0, g0, be0);
    k_aggr4<false><<<AGGR_GRID, 512>>>(1);
    // layer 2
    k_gemm_tf32<<<GEMM_GRID, 256>>>(Wc2, 1, g1, be1);
    k_aggr4<false><<<AGGR_GRID, 512>>>(2);

    // pooling + head (pool/fc1 fused)
    k_poolfc1<<<N_GRAPHS / 8, 256>>>(g2, be2, W1);
    k_fc2<<<N_GRAPHS / 8, 256>>>(W2, b2, gf, bf, out);
}